// round 12
// baseline (speedup 1.0000x reference)
#include <cuda_runtime.h>
#include <math.h>

// ---------------- problem constants ----------------
#define Bq   2
#define Sq   2048
#define Dq   1024
#define Hq   16
#define HDq  64
#define Fq   4096
#define Eq   8
#define Kq   2
#define Tq   (Bq*Sq)          // 4096 tokens
#define RCAP 9216             // 8192 assignments + 8*128 padding, /128

// ---------------- static device scratch ----------------
__device__ float g_h1[Tq*Dq];
__device__ float g_qb[Tq*Dq];
__device__ float g_kb[Tq*Dq];
__device__ float g_vb[Tq*Dq];
__device__ float g_attn[Tq*Dq];
__device__ float g_h[Tq*Dq];
__device__ float g_h2[Tq*Dq];
__device__ int   g_topi[Tq*Kq];
__device__ float g_topv[Tq*Kq];
__device__ int   g_cnt[Eq];
__device__ int   g_off[Eq+1];
__device__ int   g_rowtok[RCAP];
__device__ int   g_rowpos[Tq*Kq];
__device__ float g_hidden[(size_t)RCAP*Fq];
__device__ float g_y[(size_t)RCAP*Dq];

// ---------------- rmsnorm ----------------
__global__ void rmsnorm_kernel(const float* __restrict__ x,
                               const float* __restrict__ w,
                               float* __restrict__ out) {
    int t = blockIdx.x;
    const float* xr = x + (size_t)t * Dq;
    __shared__ float red[256];
    float s = 0.f;
    for (int d = threadIdx.x; d < Dq; d += 256) { float v = xr[d]; s += v*v; }
    red[threadIdx.x] = s; __syncthreads();
    for (int ofs = 128; ofs > 0; ofs >>= 1) {
        if (threadIdx.x < ofs) red[threadIdx.x] += red[threadIdx.x + ofs];
        __syncthreads();
    }
    float r = rsqrtf(red[0] / (float)Dq + 1e-5f);
    float* o = out + (size_t)t * Dq;
    for (int d = threadIdx.x; d < Dq; d += 256) o[d] = xr[d] * r * w[d];
}

// ---------------- generic 128x128x16 fp32 GEMM (optional residual) ----------------
// C[M x N] = A[M x Kd] @ B[Kd x N] (+ Res). grid = (N/128, M/128), block 256.
__global__ void gemm128(const float* __restrict__ A, const float* __restrict__ B,
                        const float* __restrict__ Res, float* __restrict__ C,
                        int N, int Kd) {
    __shared__ float As[16][128];
    __shared__ float Bs[16][128];
    int tid = threadIdx.x;
    int tx = tid & 15, ty = tid >> 4;
    int m0 = blockIdx.y * 128, n0 = blockIdx.x * 128;
    float acc[8][8] = {};
    for (int k0 = 0; k0 < Kd; k0 += 16) {
        #pragma unroll
        for (int l = 0; l < 2; l++) {
            int idx = l * 256 + tid; int m = idx >> 2, kq = idx & 3;
            float4 v = *(const float4*)(A + (size_t)(m0 + m) * Kd + k0 + kq * 4);
            As[kq*4+0][m] = v.x; As[kq*4+1][m] = v.y;
            As[kq*4+2][m] = v.z; As[kq*4+3][m] = v.w;
        }
        #pragma unroll
        for (int l = 0; l < 2; l++) {
            int idx = l * 256 + tid; int k = idx >> 5, n4 = idx & 31;
            *(float4*)(&Bs[k][n4*4]) = *(const float4*)(B + (size_t)(k0 + k) * N + n0 + n4 * 4);
        }
        __syncthreads();
        #pragma unroll
        for (int k = 0; k < 16; k++) {
            float a[8], b[8];
            #pragma unroll
            for (int i = 0; i < 8; i++) a[i] = As[k][ty*8 + i];
            #pragma unroll
            for (int j = 0; j < 8; j++) b[j] = Bs[k][tx*8 + j];
            #pragma unroll
            for (int i = 0; i < 8; i++)
                #pragma unroll
                for (int j = 0; j < 8; j++) acc[i][j] += a[i]*b[j];
        }
        __syncthreads();
    }
    #pragma unroll
    for (int i = 0; i < 8; i++) {
        size_t row = (size_t)(m0 + ty*8 + i) * N + n0 + tx*8;
        #pragma unroll
        for (int j = 0; j < 8; j++) {
            float v = acc[i][j];
            if (Res) v += Res[row + j];
            C[row + j] = v;
        }
    }
}

// ---------------- RoPE (in place on q,k) ----------------
__global__ void rope_kernel(float* __restrict__ q, float* __restrict__ k,
                            const int* __restrict__ pos) {
    int idx = blockIdx.x * 256 + threadIdx.x;       // over Tq*Hq*32
    if (idx >= Tq*Hq*32) return;
    int i = idx & 31;
    int h = (idx >> 5) & (Hq - 1);
    int t = idx >> 9;
    // inv_freq = 10000^(-i/32)
    float inv = expf(-(float)i * (9.2103403719761836f / 32.f));
    float ang = (float)pos[t] * inv;
    float sn, cs; sincosf(ang, &sn, &cs);
    size_t base = (size_t)t * Dq + h * HDq + 2 * i;
    float x1 = q[base], x2 = q[base+1];
    q[base]   = x1*cs - x2*sn;
    q[base+1] = x1*sn + x2*cs;
    x1 = k[base]; x2 = k[base+1];
    k[base]   = x1*cs - x2*sn;
    k[base+1] = x1*sn + x2*cs;
}

// ---------------- causal flash attention, 64-row Q tile, 32-row K tile ----------------
// grid = (Sq/64, Bq*Hq), block 256. fp32 throughout.
// QsT: [d][m] 64x(64+1). KsT: [d][m] 64x(32+1) -- FIXED SIZE (was 32*65: overflow race).
__global__ void attn_kernel(const float* __restrict__ q, const float* __restrict__ k,
                            const float* __restrict__ v, float* __restrict__ o) {
    __shared__ float QsT[64*65];
    __shared__ float KsT[64*33];
    __shared__ float PsT[32*65];
    __shared__ float Vs [32*64];
    int tid = threadIdx.x, tx = tid & 15, ty = tid >> 4;
    int bh = blockIdx.y; int b = bh >> 4, h = bh & 15;
    int qt = blockIdx.x; int q0 = qt * 64;
    size_t tokb = (size_t)b * Sq;

    #pragma unroll
    for (int l = 0; l < 4; l++) {
        int idx = l*256 + tid; int m = idx >> 4, d4 = idx & 15;
        float4 val = *(const float4*)(q + (tokb + q0 + m) * Dq + h*HDq + d4*4);
        QsT[(d4*4+0)*65 + m] = val.x; QsT[(d4*4+1)*65 + m] = val.y;
        QsT[(d4*4+2)*65 + m] = val.z; QsT[(d4*4+3)*65 + m] = val.w;
    }
    float accO[4][4] = {};
    float mrow[4], lrow[4];
    #pragma unroll
    for (int i = 0; i < 4; i++) { mrow[i] = -1e30f; lrow[i] = 0.f; }
    __syncthreads();

    int ktmax = 2*qt + 1;
    for (int kt = 0; kt <= ktmax; kt++) {
        int k0 = kt * 32;
        #pragma unroll
        for (int l = 0; l < 2; l++) {
            int idx = l*256 + tid; int m = idx >> 4, d4 = idx & 15;
            float4 kv = *(const float4*)(k + (tokb + k0 + m) * Dq + h*HDq + d4*4);
            KsT[(d4*4+0)*33 + m] = kv.x; KsT[(d4*4+1)*33 + m] = kv.y;
            KsT[(d4*4+2)*33 + m] = kv.z; KsT[(d4*4+3)*33 + m] = kv.w;
            float4 vv = *(const float4*)(v + (tokb + k0 + m) * Dq + h*HDq + d4*4);
            *(float4*)(&Vs[m*64 + d4*4]) = vv;
        }
        __syncthreads();

        float s[4][2] = {};
        #pragma unroll 16
        for (int d = 0; d < 64; d++) {
            float a0 = QsT[d*65 + ty*4+0], a1 = QsT[d*65 + ty*4+1];
            float a2 = QsT[d*65 + ty*4+2], a3 = QsT[d*65 + ty*4+3];
            float b0 = KsT[d*33 + tx*2+0], b1 = KsT[d*33 + tx*2+1];
            s[0][0] += a0*b0; s[0][1] += a0*b1;
            s[1][0] += a1*b0; s[1][1] += a1*b1;
            s[2][0] += a2*b0; s[2][1] += a2*b1;
            s[3][0] += a3*b0; s[3][1] += a3*b1;
        }
        bool domask = (kt >= 2*qt);
        #pragma unroll
        for (int i = 0; i < 4; i++)
            #pragma unroll
            for (int j = 0; j < 2; j++) {
                float val = s[i][j] * 0.125f;
                if (domask && (k0 + tx*2 + j) > (q0 + ty*4 + i)) val = -1.0e9f;
                s[i][j] = val;
            }
        #pragma unroll
        for (int i = 0; i < 4; i++) {
            float m_ = fmaxf(s[i][0], s[i][1]);
            #pragma unroll
            for (int ofs = 8; ofs; ofs >>= 1)
                m_ = fmaxf(m_, __shfl_xor_sync(0xffffffffu, m_, ofs));
            float newm = fmaxf(mrow[i], m_);
            float sum = 0.f;
            #pragma unroll
            for (int j = 0; j < 2; j++) {
                float p = __expf(s[i][j] - newm); s[i][j] = p; sum += p;
            }
            #pragma unroll
            for (int ofs = 8; ofs; ofs >>= 1)
                sum += __shfl_xor_sync(0xffffffffu, sum, ofs);
            float corr = __expf(mrow[i] - newm);
            lrow[i] = lrow[i] * corr + sum;
            mrow[i] = newm;
            #pragma unroll
            for (int c = 0; c < 4; c++) accO[i][c] *= corr;
        }
        #pragma unroll
        for (int i = 0; i < 4; i++)
            #pragma unroll
            for (int j = 0; j < 2; j++)
                PsT[(tx*2 + j)*65 + ty*4 + i] = s[i][j];
        __syncthreads();
        #pragma unroll
        for (int n = 0; n < 32; n++) {
            float p0 = PsT[n*65 + ty*4+0], p1 = PsT[n*65 + ty*4+1];
            float p2 = PsT[n*65 + ty*4+2], p3 = PsT[n*65 + ty*4+3];
            float4 vv = *(const float4*)(&Vs[n*64 + tx*4]);
            accO[0][0] += p0*vv.x; accO[0][1] += p0*vv.y; accO[0][2] += p0*vv.z; accO[0][3] += p0*vv.w;
            accO[1][0] += p1*vv.x; accO[1][1] += p1*vv.y; accO[1][2] += p1*vv.z; accO[1][3] += p1*vv.w;
            accO[2][0] += p2*vv.x; accO[2][1] += p2*vv.y; accO[2][2] += p2*vv.z; accO[2][3] += p2*vv.w;
            accO[3][0] += p3*vv.x; accO[3][1] += p3*vv.y; accO[3][2] += p3*vv.z; accO[3][3] += p3*vv.w;
        }
        __syncthreads();
    }
    #pragma unroll
    for (int i = 0; i < 4; i++) {
        float invl = 1.f / lrow[i];
        float4 ov = make_float4(accO[i][0]*invl, accO[i][1]*invl,
                                accO[i][2]*invl, accO[i][3]*invl);
        *(float4*)(o + (tokb + q0 + ty*4 + i) * Dq + h*HDq + tx*4) = ov;
    }
}

// ---------------- MoE gate: logits -> softmax -> top2 -> normalized weights ----------------
__global__ void gate_kernel(const float* __restrict__ h2, const float* __restrict__ gw,
                            int* __restrict__ topi, float* __restrict__ topv,
                            int* __restrict__ cnt) {
    int t = blockIdx.x;
    __shared__ float part[128*Eq];
    __shared__ float logit[Eq];
    float acc[Eq] = {};
    const float* x = h2 + (size_t)t * Dq;
    for (int d = threadIdx.x; d < Dq; d += 128) {
        float xv = x[d];
        #pragma unroll
        for (int e = 0; e < Eq; e++) acc[e] += xv * gw[d*Eq + e];
    }
    #pragma unroll
    for (int e = 0; e < Eq; e++) part[threadIdx.x*Eq + e] = acc[e];
    __syncthreads();
    if (threadIdx.x < Eq) {
        float s = 0.f;
        for (int i = 0; i < 128; i++) s += part[i*Eq + threadIdx.x];
        logit[threadIdx.x] = s;
    }
    __syncthreads();
    if (threadIdx.x == 0) {
        float mx = logit[0];
        #pragma unroll
        for (int e = 1; e < Eq; e++) mx = fmaxf(mx, logit[e]);
        float p[Eq];
        #pragma unroll
        for (int e = 0; e < Eq; e++) p[e] = expf(logit[e] - mx);
        int i0 = 0;
        #pragma unroll
        for (int e = 1; e < Eq; e++) if (p[e] > p[i0]) i0 = e;
        int i1 = (i0 == 0) ? 1 : 0;
        #pragma unroll
        for (int e = 0; e < Eq; e++) if (e != i0 && p[e] > p[i1]) i1 = e;
        float inv = 1.f / (p[i0] + p[i1]);
        topi[t*2]   = i0; topi[t*2+1] = i1;
        topv[t*2]   = p[i0]*inv; topv[t*2+1] = p[i1]*inv;
        atomicAdd(&cnt[i0], 1);
        atomicAdd(&cnt[i1], 1);
    }
}

__global__ void zero_cnt_kernel(int* cnt) {
    if (threadIdx.x < Eq) cnt[threadIdx.x] = 0;
}

__global__ void offsets_kernel(const int* __restrict__ cnt, int* __restrict__ off) {
    if (threadIdx.x == 0) {
        int acc = 0; off[0] = 0;
        for (int e = 0; e < Eq; e++) { acc += (cnt[e] + 127) & ~127; off[e+1] = acc; }
    }
}

// deterministic scatter: block e scans assignments in (token,k) order with a block scan
__global__ void scatter_kernel(const int* __restrict__ topi, const int* __restrict__ off,
                               int* __restrict__ rowtok, int* __restrict__ rowpos) {
    int e = blockIdx.x;
    __shared__ int sflag[256];
    __shared__ int sbase;
    int base = off[e];
    if (threadIdx.x == 0) sbase = 0;
    __syncthreads();
    for (int c = 0; c < Tq*Kq; c += 256) {
        int a = c + threadIdx.x;
        int f = (topi[a] == e) ? 1 : 0;
        sflag[threadIdx.x] = f;
        __syncthreads();
        for (int ofs = 1; ofs < 256; ofs <<= 1) {
            int v = (threadIdx.x >= ofs) ? sflag[threadIdx.x - ofs] : 0;
            __syncthreads();
            sflag[threadIdx.x] += v;
            __syncthreads();
        }
        if (f) {
            int pos = base + sbase + sflag[threadIdx.x] - 1;
            rowtok[pos] = a >> 1;
            rowpos[a] = pos;
        }
        __syncthreads();
        if (threadIdx.x == 0) sbase += sflag[255];
        __syncthreads();
    }
    for (int p = base + sbase + threadIdx.x; p < off[e+1]; p += 256) rowtok[p] = -1;
}

// ---------------- MoE up: hidden = silu(Xg @ w1[e]) * (Xg @ w3[e]) ----------------
// grid = (Fq/64, RCAP/128), block 256. Gathered A rows, dual B tiles.
__global__ void moe_up_kernel(const float* __restrict__ h2, const float* __restrict__ w1,
                              const float* __restrict__ w3, const int* __restrict__ off,
                              const int* __restrict__ rowtok, float* __restrict__ hidden) {
    __shared__ float As [16][128];
    __shared__ float B1s[16][64];
    __shared__ float B3s[16][64];
    __shared__ int   stok[128];
    __shared__ int   soff[Eq+1];
    int tid = threadIdx.x;
    if (tid <= Eq) soff[tid] = off[tid];
    __syncthreads();
    int r0 = blockIdx.y * 128;
    if (r0 >= soff[Eq]) return;
    int e = 0;
    #pragma unroll
    for (int i = 0; i < Eq; i++) if (r0 >= soff[i+1]) e = i + 1;
    if (tid < 128) stok[tid] = rowtok[r0 + tid];
    __syncthreads();
    const float* B1 = w1 + (size_t)e * Dq * Fq;
    const float* B3 = w3 + (size_t)e * Dq * Fq;
    int n0 = blockIdx.x * 64;
    int tx = tid & 15, ty = tid >> 4;
    float acc1[8][4] = {}, acc3[8][4] = {};
    for (int k0 = 0; k0 < Dq; k0 += 16) {
        #pragma unroll
        for (int l = 0; l < 2; l++) {
            int idx = l*256 + tid; int m = idx >> 2, kq = idx & 3;
            int tok = stok[m];
            float4 v = make_float4(0.f, 0.f, 0.f, 0.f);
            if (tok >= 0) v = *(const float4*)(h2 + (size_t)tok * Dq + k0 + kq*4);
            As[kq*4+0][m] = v.x; As[kq*4+1][m] = v.y;
            As[kq*4+2][m] = v.z; As[kq*4+3][m] = v.w;
        }
        {
            int k = tid >> 4, n4 = tid & 15;
            *(float4*)(&B1s[k][n4*4]) = *(const float4*)(B1 + (size_t)(k0+k)*Fq + n0 + n4*4);
            *(float4*)(&B3s[k][n4*4]) = *(const float4*)(B3 + (size_t)(k0+k)*Fq + n0 + n4*4);
        }
        __syncthreads();
        #pragma unroll
        for (int k = 0; k < 16; k++) {
            float a[8], b1[4], b3[4];
            #pragma unroll
            for (int i = 0; i < 8; i++) a[i] = As[k][ty*8 + i];
            #pragma unroll
            for (int j = 0; j < 4; j++) { b1[j] = B1s[k][tx*4+j]; b3[j] = B3s[k][tx*4+j]; }
            #pragma unroll
            for (int i = 0; i < 8; i++)
                #pragma unroll
                for (int j = 0; j < 4; j++) {
                    acc1[i][j] += a[i]*b1[j];
                    acc3[i][j] += a[i]*b3[j];
                }
        }
        __syncthreads();
    }
    #pragma unroll
    for (int i = 0; i < 8; i++) {
        size_t row = (size_t)(r0 + ty*8 + i) * Fq + n0 + tx*4;
        #pragma unroll
        for (int j = 0; j < 4; j++) {
            float u = acc1[i][j];
            float g = u / (1.f + expf(-u));
            hidden[row + j] = g * acc3[i][j];
        }
    }
}

// ---------------- MoE down: y = hidden @ w2[e] ----------------
// grid = (Dq/128, RCAP/128), block 256.
__global__ void moe_down_kernel(const float* __restrict__ hidden, const float* __restrict__ w2,
                                const int* __restrict__ off, float* __restrict__ y) {
    __shared__ float As[16][128];
    __shared__ float Bs[16][128];
    __shared__ int   soff[Eq+1];
    int tid = threadIdx.x;
    if (tid <= Eq) soff[tid] = off[tid];
    __syncthreads();
    int r0 = blockIdx.y * 128;
    if (r0 >= soff[Eq]) return;
    int e = 0;
    #pragma unroll
    for (int i = 0; i < Eq; i++) if (r0 >= soff[i+1]) e = i + 1;
    const float* Bm = w2 + (size_t)e * Fq * Dq;
    int n0 = blockIdx.x * 128;
    int tx = tid & 15, ty = tid >> 4;
    float acc[8][8] = {};
    for (int k0 = 0; k0 < Fq; k0 += 16) {
        #pragma unroll
        for (int l = 0; l < 2; l++) {
            int idx = l*256 + tid; int m = idx >> 2, kq = idx & 3;
            float4 v = *(const float4*)(hidden + (size_t)(r0 + m) * Fq + k0 + kq*4);
            As[kq*4+0][m] = v.x; As[kq*4+1][m] = v.y;
            As[kq*4+2][m] = v.z; As[kq*4+3][m] = v.w;
        }
        #pragma unroll
        for (int l = 0; l < 2; l++) {
            int idx = l*256 + tid; int k = idx >> 5, n4 = idx & 31;
            *(float4*)(&Bs[k][n4*4]) = *(const float4*)(Bm + (size_t)(k0 + k)*Dq + n0 + n4*4);
        }
        __syncthreads();
        #pragma unroll
        for (int k = 0; k < 16; k++) {
            float a[8], b[8];
            #pragma unroll
            for (int i = 0; i < 8; i++) a[i] = As[k][ty*8 + i];
            #pragma unroll
            for (int j = 0; j < 8; j++) b[j] = Bs[k][tx*8 + j];
            #pragma unroll
            for (int i = 0; i < 8; i++)
                #pragma unroll
                for (int j = 0; j < 8; j++) acc[i][j] += a[i]*b[j];
        }
        __syncthreads();
    }
    #pragma unroll
    for (int i = 0; i < 8; i++) {
        size_t row = (size_t)(r0 + ty*8 + i) * Dq + n0 + tx*8;
        #pragma unroll
        for (int j = 0; j < 8; j++) y[row + j] = acc[i][j];
    }
}

// ---------------- combine: out = h + w0*y[p0] + w1*y[p1] ----------------
__global__ void combine_kernel(const float* __restrict__ h, const float* __restrict__ y,
                               const int* __restrict__ rowpos, const float* __restrict__ topv,
                               float* __restrict__ out) {
    int idx = blockIdx.x * 256 + threadIdx.x;   // over Tq*Dq
    int t = idx >> 10;
    int d = idx & 1023;
    int p0 = rowpos[t*2], p1 = rowpos[t*2+1];
    float w0 = topv[t*2], w1 = topv[t*2+1];
    out[idx] = h[idx] + w0 * y[(size_t)p0 * Dq + d] + w1 * y[(size_t)p1 * Dq + d];
}

// ---------------- launch ----------------
extern "C" void kernel_launch(void* const* d_in, const int* in_sizes, int n_in,
                              void* d_out, int out_size) {
    const float* x    = (const float*)d_in[0];
    const int*   pos  = (const int*)  d_in[1];
    const float* ln1  = (const float*)d_in[2];
    const float* ln2  = (const float*)d_in[3];
    const float* wq   = (const float*)d_in[4];
    const float* wk   = (const float*)d_in[5];
    const float* wv   = (const float*)d_in[6];
    const float* wo   = (const float*)d_in[7];
    const float* gw   = (const float*)d_in[8];
    const float* w1   = (const float*)d_in[9];
    const float* w3   = (const float*)d_in[10];
    const float* w2   = (const float*)d_in[11];
    float* out = (float*)d_out;

    float *h1, *qb, *kb, *vb, *attnb, *hb, *h2b, *hid, *yb, *topv;
    int *topi, *cnt, *off, *rowtok, *rowpos;
    cudaGetSymbolAddress((void**)&h1,     g_h1);
    cudaGetSymbolAddress((void**)&qb,     g_qb);
    cudaGetSymbolAddress((void**)&kb,     g_kb);
    cudaGetSymbolAddress((void**)&vb,     g_vb);
    cudaGetSymbolAddress((void**)&attnb,  g_attn);
    cudaGetSymbolAddress((void**)&hb,     g_h);
    cudaGetSymbolAddress((void**)&h2b,    g_h2);
    cudaGetSymbolAddress((void**)&hid,    g_hidden);
    cudaGetSymbolAddress((void**)&yb,     g_y);
    cudaGetSymbolAddress((void**)&topv,   g_topv);
    cudaGetSymbolAddress((void**)&topi,   g_topi);
    cudaGetSymbolAddress((void**)&cnt,    g_cnt);
    cudaGetSymbolAddress((void**)&off,    g_off);
    cudaGetSymbolAddress((void**)&rowtok, g_rowtok);
    cudaGetSymbolAddress((void**)&rowpos, g_rowpos);

    dim3 gproj(Dq/128, Tq/128);   // (8, 32)

    rmsnorm_kernel<<<Tq, 256>>>(x, ln1, h1);
    gemm128<<<gproj, 256>>>(h1, wq, nullptr, qb, Dq, Dq);
    gemm128<<<gproj, 256>>>(h1, wk, nullptr, kb, Dq, Dq);
    gemm128<<<gproj, 256>>>(h1, wv, nullptr, vb, Dq, Dq);
    rope_kernel<<<(Tq*Hq*32)/256, 256>>>(qb, kb, pos);
    attn_kernel<<<dim3(Sq/64, Bq*Hq), 256>>>(qb, kb, vb, attnb);
    gemm128<<<gproj, 256>>>(attnb, wo, x, hb, Dq, Dq);
    rmsnorm_kernel<<<Tq, 256>>>(hb, ln2, h2b);

    zero_cnt_kernel<<<1, 32>>>(cnt);
    gate_kernel<<<Tq, 128>>>(h2b, gw, topi, topv, cnt);
    offsets_kernel<<<1, 32>>>(cnt, off);
    scatter_kernel<<<Eq, 256>>>(topi, off, rowtok, rowpos);
    moe_up_kernel<<<dim3(Fq/64, RCAP/128), 256>>>(h2b, w1, w3, off, rowtok, hid);
    moe_down_kernel<<<dim3(Dq/128, RCAP/128), 256>>>(hid, w2, off, yb);
    combine_kernel<<<(Tq*Dq)/256, 256>>>(hb, yb, rowpos, topv, out);
}

// round 13
// speedup vs baseline: 2.0962x; 2.0962x over previous
#include <cuda_runtime.h>
#include <math.h>
#include <stdint.h>

// ---------------- problem constants ----------------
#define Bq   2
#define Sq   2048
#define Dq   1024
#define Hq   16
#define HDq  64
#define Fq   4096
#define Eq   8
#define Kq   2
#define Tq   (Bq*Sq)          // 4096 tokens
#define RCAP 9216             // 8192 assignments + 8*128 padding, /128

// ---------------- static device scratch ----------------
__device__ float g_h1[Tq*Dq];
__device__ float g_qb[Tq*Dq];
__device__ float g_kb[Tq*Dq];
__device__ float g_vb[Tq*Dq];
__device__ float g_attn[Tq*Dq];
__device__ float g_h[Tq*Dq];
__device__ float g_h2[Tq*Dq];
__device__ int   g_topi[Tq*Kq];
__device__ float g_topv[Tq*Kq];
__device__ int   g_cnt[Eq];
__device__ int   g_off[Eq+1];
__device__ int   g_rowtok[RCAP];
__device__ int   g_rowpos[Tq*Kq];
__device__ float g_hidden[(size_t)RCAP*Fq];
__device__ float g_y[(size_t)RCAP*Dq];

// ---------------- tf32 mma helpers ----------------
__device__ __forceinline__ uint32_t f2tf(float f) {
    uint32_t u;
    asm("cvt.rna.tf32.f32 %0, %1;" : "=r"(u) : "f"(f));
    return u;
}
__device__ __forceinline__ void mma_tf32(float* c,
        uint32_t a0, uint32_t a1, uint32_t a2, uint32_t a3,
        uint32_t b0, uint32_t b1) {
    asm volatile(
        "mma.sync.aligned.m16n8k8.row.col.f32.tf32.tf32.f32 "
        "{%0,%1,%2,%3}, {%4,%5,%6,%7}, {%8,%9}, {%0,%1,%2,%3};\n"
        : "+f"(c[0]), "+f"(c[1]), "+f"(c[2]), "+f"(c[3])
        : "r"(a0), "r"(a1), "r"(a2), "r"(a3), "r"(b0), "r"(b1));
}

// ---------------- rmsnorm ----------------
__global__ void rmsnorm_kernel(const float* __restrict__ x,
                               const float* __restrict__ w,
                               float* __restrict__ out) {
    int t = blockIdx.x;
    const float* xr = x + (size_t)t * Dq;
    __shared__ float red[256];
    float s = 0.f;
    for (int d = threadIdx.x; d < Dq; d += 256) { float v = xr[d]; s += v*v; }
    red[threadIdx.x] = s; __syncthreads();
    for (int ofs = 128; ofs > 0; ofs >>= 1) {
        if (threadIdx.x < ofs) red[threadIdx.x] += red[threadIdx.x + ofs];
        __syncthreads();
    }
    float r = rsqrtf(red[0] / (float)Dq + 1e-5f);
    float* o = out + (size_t)t * Dq;
    for (int d = threadIdx.x; d < Dq; d += 256) o[d] = xr[d] * r * w[d];
}

// ---------------- tf32 tensor-core GEMM 128x128x32 (optional residual) ----------------
// C[M x N] = A[M x Kd] @ B[Kd x N] (+ Res). grid = (N/128, M/128), block 256.
__global__ void __launch_bounds__(256) gemm_tf32(
        const float* __restrict__ A, const float* __restrict__ B,
        const float* __restrict__ Res, float* __restrict__ C,
        int N, int Kd) {
    __shared__ uint32_t As[128][36];   // bank = (4m + k) % 32 : conflict-free frags
    __shared__ uint32_t Bs[32][136];   // bank = (8k + n) % 32 : conflict-free frags
    int tid = threadIdx.x, lane = tid & 31, wid = tid >> 5;
    int wm = (wid & 3) * 32, wn = (wid >> 2) * 64;
    int m0 = blockIdx.y * 128, n0 = blockIdx.x * 128;
    int lr = lane >> 2, lc = lane & 3;
    float acc[2][8][4] = {};

    for (int k0 = 0; k0 < Kd; k0 += 32) {
        #pragma unroll
        for (int p = 0; p < 4; p++) {
            int idx = p * 256 + tid; int m = idx >> 3, kc = idx & 7;
            float4 v = *(const float4*)(A + (size_t)(m0 + m) * Kd + k0 + kc * 4);
            As[m][kc*4+0] = f2tf(v.x); As[m][kc*4+1] = f2tf(v.y);
            As[m][kc*4+2] = f2tf(v.z); As[m][kc*4+3] = f2tf(v.w);
        }
        #pragma unroll
        for (int p = 0; p < 4; p++) {
            int idx = p * 256 + tid; int k = idx >> 5, nc = idx & 31;
            float4 v = *(const float4*)(B + (size_t)(k0 + k) * N + n0 + nc * 4);
            Bs[k][nc*4+0] = f2tf(v.x); Bs[k][nc*4+1] = f2tf(v.y);
            Bs[k][nc*4+2] = f2tf(v.z); Bs[k][nc*4+3] = f2tf(v.w);
        }
        __syncthreads();
        #pragma unroll
        for (int kk = 0; kk < 4; kk++) {
            int kb = kk * 8;
            uint32_t a[2][4];
            #pragma unroll
            for (int mi = 0; mi < 2; mi++) {
                int rb = wm + mi * 16;
                a[mi][0] = As[rb + lr     ][kb + lc    ];
                a[mi][1] = As[rb + lr + 8 ][kb + lc    ];
                a[mi][2] = As[rb + lr     ][kb + lc + 4];
                a[mi][3] = As[rb + lr + 8 ][kb + lc + 4];
            }
            #pragma unroll
            for (int ni = 0; ni < 8; ni++) {
                int nb = wn + ni * 8;
                uint32_t b0 = Bs[kb + lc    ][nb + lr];
                uint32_t b1 = Bs[kb + lc + 4][nb + lr];
                mma_tf32(acc[0][ni], a[0][0], a[0][1], a[0][2], a[0][3], b0, b1);
                mma_tf32(acc[1][ni], a[1][0], a[1][1], a[1][2], a[1][3], b0, b1);
            }
        }
        __syncthreads();
    }
    #pragma unroll
    for (int mi = 0; mi < 2; mi++) {
        int r0 = m0 + wm + mi * 16 + lr;
        #pragma unroll
        for (int ni = 0; ni < 8; ni++) {
            int c0 = n0 + wn + ni * 8 + lc * 2;
            float2 v0 = make_float2(acc[mi][ni][0], acc[mi][ni][1]);
            float2 v1 = make_float2(acc[mi][ni][2], acc[mi][ni][3]);
            if (Res) {
                const float2 r0v = *(const float2*)(Res + (size_t)r0 * N + c0);
                const float2 r1v = *(const float2*)(Res + (size_t)(r0+8) * N + c0);
                v0.x += r0v.x; v0.y += r0v.y; v1.x += r1v.x; v1.y += r1v.y;
            }
            *(float2*)(C + (size_t)r0 * N + c0) = v0;
            *(float2*)(C + (size_t)(r0 + 8) * N + c0) = v1;
        }
    }
}

// ---------------- RoPE (in place on q,k) ----------------
__global__ void rope_kernel(float* __restrict__ q, float* __restrict__ k,
                            const int* __restrict__ pos) {
    int idx = blockIdx.x * 256 + threadIdx.x;       // over Tq*Hq*32
    if (idx >= Tq*Hq*32) return;
    int i = idx & 31;
    int h = (idx >> 5) & (Hq - 1);
    int t = idx >> 9;
    float inv = expf(-(float)i * (9.2103403719761836f / 32.f));
    float ang = (float)pos[t] * inv;
    float sn, cs; sincosf(ang, &sn, &cs);
    size_t base = (size_t)t * Dq + h * HDq + 2 * i;
    float x1 = q[base], x2 = q[base+1];
    q[base]   = x1*cs - x2*sn;
    q[base+1] = x1*sn + x2*cs;
    x1 = k[base]; x2 = k[base+1];
    k[base]   = x1*cs - x2*sn;
    k[base+1] = x1*sn + x2*cs;
}

// ---------------- causal flash attention (fp32), 64-row Q tile, 32-row K tile --------
__global__ void attn_kernel(const float* __restrict__ q, const float* __restrict__ k,
                            const float* __restrict__ v, float* __restrict__ o) {
    __shared__ float QsT[64*65];
    __shared__ float KsT[64*33];
    __shared__ float PsT[32*65];
    __shared__ float Vs [32*64];
    int tid = threadIdx.x, tx = tid & 15, ty = tid >> 4;
    int bh = blockIdx.y; int b = bh >> 4, h = bh & 15;
    int qt = blockIdx.x; int q0 = qt * 64;
    size_t tokb = (size_t)b * Sq;

    #pragma unroll
    for (int l = 0; l < 4; l++) {
        int idx = l*256 + tid; int m = idx >> 4, d4 = idx & 15;
        float4 val = *(const float4*)(q + (tokb + q0 + m) * Dq + h*HDq + d4*4);
        QsT[(d4*4+0)*65 + m] = val.x; QsT[(d4*4+1)*65 + m] = val.y;
        QsT[(d4*4+2)*65 + m] = val.z; QsT[(d4*4+3)*65 + m] = val.w;
    }
    float accO[4][4] = {};
    float mrow[4], lrow[4];
    #pragma unroll
    for (int i = 0; i < 4; i++) { mrow[i] = -1e30f; lrow[i] = 0.f; }
    __syncthreads();

    int ktmax = 2*qt + 1;
    for (int kt = 0; kt <= ktmax; kt++) {
        int k0 = kt * 32;
        #pragma unroll
        for (int l = 0; l < 2; l++) {
            int idx = l*256 + tid; int m = idx >> 4, d4 = idx & 15;
            float4 kv = *(const float4*)(k + (tokb + k0 + m) * Dq + h*HDq + d4*4);
            KsT[(d4*4+0)*33 + m] = kv.x; KsT[(d4*4+1)*33 + m] = kv.y;
            KsT[(d4*4+2)*33 + m] = kv.z; KsT[(d4*4+3)*33 + m] = kv.w;
            float4 vv = *(const float4*)(v + (tokb + k0 + m) * Dq + h*HDq + d4*4);
            *(float4*)(&Vs[m*64 + d4*4]) = vv;
        }
        __syncthreads();

        float s[4][2] = {};
        #pragma unroll 16
        for (int d = 0; d < 64; d++) {
            float a0 = QsT[d*65 + ty*4+0], a1 = QsT[d*65 + ty*4+1];
            float a2 = QsT[d*65 + ty*4+2], a3 = QsT[d*65 + ty*4+3];
            float b0 = KsT[d*33 + tx*2+0], b1 = KsT[d*33 + tx*2+1];
            s[0][0] += a0*b0; s[0][1] += a0*b1;
            s[1][0] += a1*b0; s[1][1] += a1*b1;
            s[2][0] += a2*b0; s[2][1] += a2*b1;
            s[3][0] += a3*b0; s[3][1] += a3*b1;
        }
        bool domask = (kt >= 2*qt);
        #pragma unroll
        for (int i = 0; i < 4; i++)
            #pragma unroll
            for (int j = 0; j < 2; j++) {
                float val = s[i][j] * 0.125f;
                if (domask && (k0 + tx*2 + j) > (q0 + ty*4 + i)) val = -1.0e9f;
                s[i][j] = val;
            }
        #pragma unroll
        for (int i = 0; i < 4; i++) {
            float m_ = fmaxf(s[i][0], s[i][1]);
            #pragma unroll
            for (int ofs = 8; ofs; ofs >>= 1)
                m_ = fmaxf(m_, __shfl_xor_sync(0xffffffffu, m_, ofs));
            float newm = fmaxf(mrow[i], m_);
            float sum = 0.f;
            #pragma unroll
            for (int j = 0; j < 2; j++) {
                float p = __expf(s[i][j] - newm); s[i][j] = p; sum += p;
            }
            #pragma unroll
            for (int ofs = 8; ofs; ofs >>= 1)
                sum += __shfl_xor_sync(0xffffffffu, sum, ofs);
            float corr = __expf(mrow[i] - newm);
            lrow[i] = lrow[i] * corr + sum;
            mrow[i] = newm;
            #pragma unroll
            for (int c = 0; c < 4; c++) accO[i][c] *= corr;
        }
        #pragma unroll
        for (int i = 0; i < 4; i++)
            #pragma unroll
            for (int j = 0; j < 2; j++)
                PsT[(tx*2 + j)*65 + ty*4 + i] = s[i][j];
        __syncthreads();
        #pragma unroll
        for (int n = 0; n < 32; n++) {
            float p0 = PsT[n*65 + ty*4+0], p1 = PsT[n*65 + ty*4+1];
            float p2 = PsT[n*65 + ty*4+2], p3 = PsT[n*65 + ty*4+3];
            float4 vv = *(const float4*)(&Vs[n*64 + tx*4]);
            accO[0][0] += p0*vv.x; accO[0][1] += p0*vv.y; accO[0][2] += p0*vv.z; accO[0][3] += p0*vv.w;
            accO[1][0] += p1*vv.x; accO[1][1] += p1*vv.y; accO[1][2] += p1*vv.z; accO[1][3] += p1*vv.w;
            accO[2][0] += p2*vv.x; accO[2][1] += p2*vv.y; accO[2][2] += p2*vv.z; accO[2][3] += p2*vv.w;
            accO[3][0] += p3*vv.x; accO[3][1] += p3*vv.y; accO[3][2] += p3*vv.z; accO[3][3] += p3*vv.w;
        }
        __syncthreads();
    }
    #pragma unroll
    for (int i = 0; i < 4; i++) {
        float invl = 1.f / lrow[i];
        float4 ov = make_float4(accO[i][0]*invl, accO[i][1]*invl,
                                accO[i][2]*invl, accO[i][3]*invl);
        *(float4*)(o + (tokb + q0 + ty*4 + i) * Dq + h*HDq + tx*4) = ov;
    }
}

// ---------------- MoE gate ----------------
__global__ void gate_kernel(const float* __restrict__ h2, const float* __restrict__ gw,
                            int* __restrict__ topi, float* __restrict__ topv,
                            int* __restrict__ cnt) {
    int t = blockIdx.x;
    __shared__ float part[128*Eq];
    __shared__ float logit[Eq];
    float acc[Eq] = {};
    const float* x = h2 + (size_t)t * Dq;
    for (int d = threadIdx.x; d < Dq; d += 128) {
        float xv = x[d];
        #pragma unroll
        for (int e = 0; e < Eq; e++) acc[e] += xv * gw[d*Eq + e];
    }
    #pragma unroll
    for (int e = 0; e < Eq; e++) part[threadIdx.x*Eq + e] = acc[e];
    __syncthreads();
    if (threadIdx.x < Eq) {
        float s = 0.f;
        for (int i = 0; i < 128; i++) s += part[i*Eq + threadIdx.x];
        logit[threadIdx.x] = s;
    }
    __syncthreads();
    if (threadIdx.x == 0) {
        float mx = logit[0];
        #pragma unroll
        for (int e = 1; e < Eq; e++) mx = fmaxf(mx, logit[e]);
        float p[Eq];
        #pragma unroll
        for (int e = 0; e < Eq; e++) p[e] = expf(logit[e] - mx);
        int i0 = 0;
        #pragma unroll
        for (int e = 1; e < Eq; e++) if (p[e] > p[i0]) i0 = e;
        int i1 = (i0 == 0) ? 1 : 0;
        #pragma unroll
        for (int e = 0; e < Eq; e++) if (e != i0 && p[e] > p[i1]) i1 = e;
        float inv = 1.f / (p[i0] + p[i1]);
        topi[t*2]   = i0; topi[t*2+1] = i1;
        topv[t*2]   = p[i0]*inv; topv[t*2+1] = p[i1]*inv;
        atomicAdd(&cnt[i0], 1);
        atomicAdd(&cnt[i1], 1);
    }
}

__global__ void zero_cnt_kernel(int* cnt) {
    if (threadIdx.x < Eq) cnt[threadIdx.x] = 0;
}

__global__ void offsets_kernel(const int* __restrict__ cnt, int* __restrict__ off) {
    if (threadIdx.x == 0) {
        int acc = 0; off[0] = 0;
        for (int e = 0; e < Eq; e++) { acc += (cnt[e] + 127) & ~127; off[e+1] = acc; }
    }
}

// deterministic scatter
__global__ void scatter_kernel(const int* __restrict__ topi, const int* __restrict__ off,
                               int* __restrict__ rowtok, int* __restrict__ rowpos) {
    int e = blockIdx.x;
    __shared__ int sflag[256];
    __shared__ int sbase;
    int base = off[e];
    if (threadIdx.x == 0) sbase = 0;
    __syncthreads();
    for (int c = 0; c < Tq*Kq; c += 256) {
        int a = c + threadIdx.x;
        int f = (topi[a] == e) ? 1 : 0;
        sflag[threadIdx.x] = f;
        __syncthreads();
        for (int ofs = 1; ofs < 256; ofs <<= 1) {
            int v = (threadIdx.x >= ofs) ? sflag[threadIdx.x - ofs] : 0;
            __syncthreads();
            sflag[threadIdx.x] += v;
            __syncthreads();
        }
        if (f) {
            int pos = base + sbase + sflag[threadIdx.x] - 1;
            rowtok[pos] = a >> 1;
            rowpos[a] = pos;
        }
        __syncthreads();
        if (threadIdx.x == 0) sbase += sflag[255];
        __syncthreads();
    }
    for (int p = base + sbase + threadIdx.x; p < off[e+1]; p += 256) rowtok[p] = -1;
}

// ---------------- MoE up (tf32 mma): hidden = silu(Xg@w1[e]) * (Xg@w3[e]) ----------------
// grid = (Fq/64, RCAP/128), block 256. Warp tile 32x32, dual B.
__global__ void __launch_bounds__(256) moe_up_tf32(
        const float* __restrict__ h2, const float* __restrict__ w1,
        const float* __restrict__ w3, const int* __restrict__ off,
        const int* __restrict__ rowtok, float* __restrict__ hidden) {
    __shared__ uint32_t As [128][36];
    __shared__ uint32_t B1s[32][72];
    __shared__ uint32_t B3s[32][72];
    __shared__ int stok[128];
    __shared__ int soff[Eq+1];
    int tid = threadIdx.x, lane = tid & 31, wid = tid >> 5;
    if (tid <= Eq) soff[tid] = off[tid];
    __syncthreads();
    int r0 = blockIdx.y * 128;
    if (r0 >= soff[Eq]) return;
    int e = 0;
    #pragma unroll
    for (int i = 0; i < Eq; i++) if (r0 >= soff[i+1]) e = i + 1;
    if (tid < 128) stok[tid] = rowtok[r0 + tid];
    __syncthreads();
    const float* B1 = w1 + (size_t)e * Dq * Fq;
    const float* B3 = w3 + (size_t)e * Dq * Fq;
    int n0 = blockIdx.x * 64;
    int wm = (wid & 3) * 32, wn = (wid >> 2) * 32;
    int lr = lane >> 2, lc = lane & 3;
    float acc1[2][4][4] = {}, acc3[2][4][4] = {};

    for (int k0 = 0; k0 < Dq; k0 += 32) {
        #pragma unroll
        for (int p = 0; p < 4; p++) {
            int idx = p * 256 + tid; int m = idx >> 3, kc = idx & 7;
            int tok = stok[m];
            float4 v = make_float4(0.f, 0.f, 0.f, 0.f);
            if (tok >= 0) v = *(const float4*)(h2 + (size_t)tok * Dq + k0 + kc * 4);
            As[m][kc*4+0] = f2tf(v.x); As[m][kc*4+1] = f2tf(v.y);
            As[m][kc*4+2] = f2tf(v.z); As[m][kc*4+3] = f2tf(v.w);
        }
        #pragma unroll
        for (int p = 0; p < 2; p++) {
            int idx = p * 256 + tid; int k = idx >> 4, nc = idx & 15;
            float4 v1 = *(const float4*)(B1 + (size_t)(k0 + k) * Fq + n0 + nc * 4);
            B1s[k][nc*4+0] = f2tf(v1.x); B1s[k][nc*4+1] = f2tf(v1.y);
            B1s[k][nc*4+2] = f2tf(v1.z); B1s[k][nc*4+3] = f2tf(v1.w);
            float4 v3 = *(const float4*)(B3 + (size_t)(k0 + k) * Fq + n0 + nc * 4);
            B3s[k][nc*4+0] = f2tf(v3.x); B3s[k][nc*4+1] = f2tf(v3.y);
            B3s[k][nc*4+2] = f2tf(v3.z); B3s[k][nc*4+3] = f2tf(v3.w);
        }
        __syncthreads();
        #pragma unroll
        for (int kk = 0; kk < 4; kk++) {
            int kb = kk * 8;
            uint32_t a[2][4];
            #pragma unroll
            for (int mi = 0; mi < 2; mi++) {
                int rb = wm + mi * 16;
                a[mi][0] = As[rb + lr     ][kb + lc    ];
                a[mi][1] = As[rb + lr + 8 ][kb + lc    ];
                a[mi][2] = As[rb + lr     ][kb + lc + 4];
                a[mi][3] = As[rb + lr + 8 ][kb + lc + 4];
            }
            #pragma unroll
            for (int ni = 0; ni < 4; ni++) {
                int nb = wn + ni * 8;
                uint32_t b10 = B1s[kb + lc    ][nb + lr];
                uint32_t b11 = B1s[kb + lc + 4][nb + lr];
                uint32_t b30 = B3s[kb + lc    ][nb + lr];
                uint32_t b31 = B3s[kb + lc + 4][nb + lr];
                mma_tf32(acc1[0][ni], a[0][0], a[0][1], a[0][2], a[0][3], b10, b11);
                mma_tf32(acc1[1][ni], a[1][0], a[1][1], a[1][2], a[1][3], b10, b11);
                mma_tf32(acc3[0][ni], a[0][0], a[0][1], a[0][2], a[0][3], b30, b31);
                mma_tf32(acc3[1][ni], a[1][0], a[1][1], a[1][2], a[1][3], b30, b31);
            }
        }
        __syncthreads();
    }
    #pragma unroll
    for (int mi = 0; mi < 2; mi++) {
        int row = r0 + wm + mi * 16 + lr;
        #pragma unroll
        for (int ni = 0; ni < 4; ni++) {
            int col = n0 + wn + ni * 8 + lc * 2;
            #pragma unroll
            for (int half = 0; half < 2; half++) {
                float u0 = acc1[mi][ni][half*2+0], u1 = acc1[mi][ni][half*2+1];
                float g0 = u0 / (1.f + expf(-u0));
                float g1 = u1 / (1.f + expf(-u1));
                float2 hv = make_float2(g0 * acc3[mi][ni][half*2+0],
                                        g1 * acc3[mi][ni][half*2+1]);
                *(float2*)(hidden + (size_t)(row + half*8) * Fq + col) = hv;
            }
        }
    }
}

// ---------------- MoE down (tf32 mma): y = hidden @ w2[e] ----------------
// grid = (Dq/128, RCAP/128), block 256.
__global__ void __launch_bounds__(256) moe_down_tf32(
        const float* __restrict__ hidden, const float* __restrict__ w2,
        const int* __restrict__ off, float* __restrict__ y) {
    __shared__ uint32_t As[128][36];
    __shared__ uint32_t Bs[32][136];
    __shared__ int soff[Eq+1];
    int tid = threadIdx.x, lane = tid & 31, wid = tid >> 5;
    if (tid <= Eq) soff[tid] = off[tid];
    __syncthreads();
    int r0 = blockIdx.y * 128;
    if (r0 >= soff[Eq]) return;
    int e = 0;
    #pragma unroll
    for (int i = 0; i < Eq; i++) if (r0 >= soff[i+1]) e = i + 1;
    const float* Bm = w2 + (size_t)e * Fq * Dq;
    int n0 = blockIdx.x * 128;
    int wm = (wid & 3) * 32, wn = (wid >> 2) * 64;
    int lr = lane >> 2, lc = lane & 3;
    float acc[2][8][4] = {};

    for (int k0 = 0; k0 < Fq; k0 += 32) {
        #pragma unroll
        for (int p = 0; p < 4; p++) {
            int idx = p * 256 + tid; int m = idx >> 3, kc = idx & 7;
            float4 v = *(const float4*)(hidden + (size_t)(r0 + m) * Fq + k0 + kc * 4);
            As[m][kc*4+0] = f2tf(v.x); As[m][kc*4+1] = f2tf(v.y);
            As[m][kc*4+2] = f2tf(v.z); As[m][kc*4+3] = f2tf(v.w);
        }
        #pragma unroll
        for (int p = 0; p < 4; p++) {
            int idx = p * 256 + tid; int k = idx >> 5, nc = idx & 31;
            float4 v = *(const float4*)(Bm + (size_t)(k0 + k) * Dq + n0 + nc * 4);
            Bs[k][nc*4+0] = f2tf(v.x); Bs[k][nc*4+1] = f2tf(v.y);
            Bs[k][nc*4+2] = f2tf(v.z); Bs[k][nc*4+3] = f2tf(v.w);
        }
        __syncthreads();
        #pragma unroll
        for (int kk = 0; kk < 4; kk++) {
            int kb = kk * 8;
            uint32_t a[2][4];
            #pragma unroll
            for (int mi = 0; mi < 2; mi++) {
                int rb = wm + mi * 16;
                a[mi][0] = As[rb + lr     ][kb + lc    ];
                a[mi][1] = As[rb + lr + 8 ][kb + lc    ];
                a[mi][2] = As[rb + lr     ][kb + lc + 4];
                a[mi][3] = As[rb + lr + 8 ][kb + lc + 4];
            }
            #pragma unroll
            for (int ni = 0; ni < 8; ni++) {
                int nb = wn + ni * 8;
                uint32_t b0 = Bs[kb + lc    ][nb + lr];
                uint32_t b1 = Bs[kb + lc + 4][nb + lr];
                mma_tf32(acc[0][ni], a[0][0], a[0][1], a[0][2], a[0][3], b0, b1);
                mma_tf32(acc[1][ni], a[1][0], a[1][1], a[1][2], a[1][3], b0, b1);
            }
        }
        __syncthreads();
    }
    #pragma unroll
    for (int mi = 0; mi < 2; mi++) {
        int row = r0 + wm + mi * 16 + lr;
        #pragma unroll
        for (int ni = 0; ni < 8; ni++) {
            int col = n0 + wn + ni * 8 + lc * 2;
            *(float2*)(y + (size_t)row * Dq + col) =
                make_float2(acc[mi][ni][0], acc[mi][ni][1]);
            *(float2*)(y + (size_t)(row + 8) * Dq + col) =
                make_float2(acc[mi][ni][2], acc[mi][ni][3]);
        }
    }
}

// ---------------- combine: out = h + w0*y[p0] + w1*y[p1] ----------------
__global__ void combine_kernel(const float* __restrict__ h, const float* __restrict__ y,
                               const int* __restrict__ rowpos, const float* __restrict__ topv,
                               float* __restrict__ out) {
    int idx = blockIdx.x * 256 + threadIdx.x;   // over Tq*Dq
    int t = idx >> 10;
    int d = idx & 1023;
    int p0 = rowpos[t*2], p1 = rowpos[t*2+1];
    float w0 = topv[t*2], w1 = topv[t*2+1];
    out[idx] = h[idx] + w0 * y[(size_t)p0 * Dq + d] + w1 * y[(size_t)p1 * Dq + d];
}

// ---------------- launch ----------------
extern "C" void kernel_launch(void* const* d_in, const int* in_sizes, int n_in,
                              void* d_out, int out_size) {
    const float* x    = (const float*)d_in[0];
    const int*   pos  = (const int*)  d_in[1];
    const float* ln1  = (const float*)d_in[2];
    const float* ln2  = (const float*)d_in[3];
    const float* wq   = (const float*)d_in[4];
    const float* wk   = (const float*)d_in[5];
    const float* wv   = (const float*)d_in[6];
    const float* wo   = (const float*)d_in[7];
    const float* gw   = (const float*)d_in[8];
    const float* w1   = (const float*)d_in[9];
    const float* w3   = (const float*)d_in[10];
    const float* w2   = (const float*)d_in[11];
    float* out = (float*)d_out;

    float *h1, *qb, *kb, *vb, *attnb, *hb, *h2b, *hid, *yb, *topv;
    int *topi, *cnt, *off, *rowtok, *rowpos;
    cudaGetSymbolAddress((void**)&h1,     g_h1);
    cudaGetSymbolAddress((void**)&qb,     g_qb);
    cudaGetSymbolAddress((void**)&kb,     g_kb);
    cudaGetSymbolAddress((void**)&vb,     g_vb);
    cudaGetSymbolAddress((void**)&attnb,  g_attn);
    cudaGetSymbolAddress((void**)&hb,     g_h);
    cudaGetSymbolAddress((void**)&h2b,    g_h2);
    cudaGetSymbolAddress((void**)&hid,    g_hidden);
    cudaGetSymbolAddress((void**)&yb,     g_y);
    cudaGetSymbolAddress((void**)&topv,   g_topv);
    cudaGetSymbolAddress((void**)&topi,   g_topi);
    cudaGetSymbolAddress((void**)&cnt,    g_cnt);
    cudaGetSymbolAddress((void**)&off,    g_off);
    cudaGetSymbolAddress((void**)&rowtok, g_rowtok);
    cudaGetSymbolAddress((void**)&rowpos, g_rowpos);

    dim3 gproj(Dq/128, Tq/128);   // (8, 32)

    rmsnorm_kernel<<<Tq, 256>>>(x, ln1, h1);
    gemm_tf32<<<gproj, 256>>>(h1, wq, nullptr, qb, Dq, Dq);
    gemm_tf32<<<gproj, 256>>>(h1, wk, nullptr, kb, Dq, Dq);
    gemm_tf32<<<gproj, 256>>>(h1, wv, nullptr, vb, Dq, Dq);
    rope_kernel<<<(Tq*Hq*32)/256, 256>>>(qb, kb, pos);
    attn_kernel<<<dim3(Sq/64, Bq*Hq), 256>>>(qb, kb, vb, attnb);
    gemm_tf32<<<gproj, 256>>>(attnb, wo, x, hb, Dq, Dq);
    rmsnorm_kernel<<<Tq, 256>>>(hb, ln2, h2b);

    zero_cnt_kernel<<<1, 32>>>(cnt);
    gate_kernel<<<Tq, 128>>>(h2b, gw, topi, topv, cnt);
    offsets_kernel<<<1, 32>>>(cnt, off);
    scatter_kernel<<<Eq, 256>>>(topi, off, rowtok, rowpos);
    moe_up_tf32<<<dim3(Fq/64, RCAP/128), 256>>>(h2b, w1, w3, off, rowtok, hid);
    moe_down_tf32<<<dim3(Dq/128, RCAP/128), 256>>>(hid, w2, off, yb);
    combine_kernel<<<(Tq*Dq)/256, 256>>>(hb, yb, rowpos, topv, out);
}

// round 14
// speedup vs baseline: 2.1203x; 1.0115x over previous
#include <cuda_runtime.h>
#include <math.h>
#include <stdint.h>

// ---------------- problem constants ----------------
#define Bq   2
#define Sq   2048
#define Dq   1024
#define Hq   16
#define HDq  64
#define Fq   4096
#define Eq   8
#define Kq   2
#define Tq   (Bq*Sq)          // 4096 tokens
#define RCAP 9216             // 8192 assignments + 8*128 padding, /128

// ---------------- static device scratch ----------------
__device__ float g_h1[Tq*Dq];
__device__ float g_qb[Tq*Dq];
__device__ float g_kb[Tq*Dq];
__device__ float g_vb[Tq*Dq];
__device__ float g_attn[Tq*Dq];
__device__ float g_h[Tq*Dq];
__device__ float g_h2[Tq*Dq];
__device__ int   g_topi[Tq*Kq];
__device__ float g_topv[Tq*Kq];
__device__ int   g_cnt[Eq];
__device__ int   g_off[Eq+1];
__device__ int   g_rowtok[RCAP];
__device__ int   g_rowpos[Tq*Kq];
__device__ float g_hidden[(size_t)RCAP*Fq];
__device__ float g_y[(size_t)RCAP*Dq];

// ---------------- tf32 mma helpers ----------------
__device__ __forceinline__ uint32_t f2tf(float f) {
    uint32_t u;
    asm("cvt.rna.tf32.f32 %0, %1;" : "=r"(u) : "f"(f));
    return u;
}
__device__ __forceinline__ void mma_tf32(float* c,
        uint32_t a0, uint32_t a1, uint32_t a2, uint32_t a3,
        uint32_t b0, uint32_t b1) {
    asm volatile(
        "mma.sync.aligned.m16n8k8.row.col.f32.tf32.tf32.f32 "
        "{%0,%1,%2,%3}, {%4,%5,%6,%7}, {%8,%9}, {%0,%1,%2,%3};\n"
        : "+f"(c[0]), "+f"(c[1]), "+f"(c[2]), "+f"(c[3])
        : "r"(a0), "r"(a1), "r"(a2), "r"(a3), "r"(b0), "r"(b1));
}

// ---------------- rmsnorm ----------------
__global__ void rmsnorm_kernel(const float* __restrict__ x,
                               const float* __restrict__ w,
                               float* __restrict__ out) {
    int t = blockIdx.x;
    const float* xr = x + (size_t)t * Dq;
    __shared__ float red[256];
    float s = 0.f;
    for (int d = threadIdx.x; d < Dq; d += 256) { float v = xr[d]; s += v*v; }
    red[threadIdx.x] = s; __syncthreads();
    for (int ofs = 128; ofs > 0; ofs >>= 1) {
        if (threadIdx.x < ofs) red[threadIdx.x] += red[threadIdx.x + ofs];
        __syncthreads();
    }
    float r = rsqrtf(red[0] / (float)Dq + 1e-5f);
    float* o = out + (size_t)t * Dq;
    for (int d = threadIdx.x; d < Dq; d += 256) o[d] = xr[d] * r * w[d];
}

// ---------------- tf32 tensor-core GEMM 128x128x32 (optional residual) ----------------
// C[M x N] = A[M x Kd] @ B[Kd x N] (+ Res). grid = (N/128, M/128), block 256.
__global__ void __launch_bounds__(256) gemm_tf32(
        const float* __restrict__ A, const float* __restrict__ B,
        const float* __restrict__ Res, float* __restrict__ C,
        int N, int Kd) {
    __shared__ uint32_t As[128][36];   // bank = (4m + k) % 32 : conflict-free frags
    __shared__ uint32_t Bs[32][136];   // bank = (8k + n) % 32 : conflict-free frags
    int tid = threadIdx.x, lane = tid & 31, wid = tid >> 5;
    int wm = (wid & 3) * 32, wn = (wid >> 2) * 64;
    int m0 = blockIdx.y * 128, n0 = blockIdx.x * 128;
    int lr = lane >> 2, lc = lane & 3;
    float acc[2][8][4] = {};

    for (int k0 = 0; k0 < Kd; k0 += 32) {
        #pragma unroll
        for (int p = 0; p < 4; p++) {
            int idx = p * 256 + tid; int m = idx >> 3, kc = idx & 7;
            float4 v = *(const float4*)(A + (size_t)(m0 + m) * Kd + k0 + kc * 4);
            As[m][kc*4+0] = f2tf(v.x); As[m][kc*4+1] = f2tf(v.y);
            As[m][kc*4+2] = f2tf(v.z); As[m][kc*4+3] = f2tf(v.w);
        }
        #pragma unroll
        for (int p = 0; p < 4; p++) {
            int idx = p * 256 + tid; int k = idx >> 5, nc = idx & 31;
            float4 v = *(const float4*)(B + (size_t)(k0 + k) * N + n0 + nc * 4);
            Bs[k][nc*4+0] = f2tf(v.x); Bs[k][nc*4+1] = f2tf(v.y);
            Bs[k][nc*4+2] = f2tf(v.z); Bs[k][nc*4+3] = f2tf(v.w);
        }
        __syncthreads();
        #pragma unroll
        for (int kk = 0; kk < 4; kk++) {
            int kb = kk * 8;
            uint32_t a[2][4];
            #pragma unroll
            for (int mi = 0; mi < 2; mi++) {
                int rb = wm + mi * 16;
                a[mi][0] = As[rb + lr     ][kb + lc    ];
                a[mi][1] = As[rb + lr + 8 ][kb + lc    ];
                a[mi][2] = As[rb + lr     ][kb + lc + 4];
                a[mi][3] = As[rb + lr + 8 ][kb + lc + 4];
            }
            #pragma unroll
            for (int ni = 0; ni < 8; ni++) {
                int nb = wn + ni * 8;
                uint32_t b0 = Bs[kb + lc    ][nb + lr];
                uint32_t b1 = Bs[kb + lc + 4][nb + lr];
                mma_tf32(acc[0][ni], a[0][0], a[0][1], a[0][2], a[0][3], b0, b1);
                mma_tf32(acc[1][ni], a[1][0], a[1][1], a[1][2], a[1][3], b0, b1);
            }
        }
        __syncthreads();
    }
    #pragma unroll
    for (int mi = 0; mi < 2; mi++) {
        int r0 = m0 + wm + mi * 16 + lr;
        #pragma unroll
        for (int ni = 0; ni < 8; ni++) {
            int c0 = n0 + wn + ni * 8 + lc * 2;
            float2 v0 = make_float2(acc[mi][ni][0], acc[mi][ni][1]);
            float2 v1 = make_float2(acc[mi][ni][2], acc[mi][ni][3]);
            if (Res) {
                const float2 r0v = *(const float2*)(Res + (size_t)r0 * N + c0);
                const float2 r1v = *(const float2*)(Res + (size_t)(r0+8) * N + c0);
                v0.x += r0v.x; v0.y += r0v.y; v1.x += r1v.x; v1.y += r1v.y;
            }
            *(float2*)(C + (size_t)r0 * N + c0) = v0;
            *(float2*)(C + (size_t)(r0 + 8) * N + c0) = v1;
        }
    }
}

// ---------------- RoPE (in place on q,k) ----------------
__global__ void rope_kernel(float* __restrict__ q, float* __restrict__ k,
                            const int* __restrict__ pos) {
    int idx = blockIdx.x * 256 + threadIdx.x;       // over Tq*Hq*32
    if (idx >= Tq*Hq*32) return;
    int i = idx & 31;
    int h = (idx >> 5) & (Hq - 1);
    int t = idx >> 9;
    float inv = expf(-(float)i * (9.2103403719761836f / 32.f));
    float ang = (float)pos[t] * inv;
    float sn, cs; sincosf(ang, &sn, &cs);
    size_t base = (size_t)t * Dq + h * HDq + 2 * i;
    float x1 = q[base], x2 = q[base+1];
    q[base]   = x1*cs - x2*sn;
    q[base+1] = x1*sn + x2*cs;
    x1 = k[base]; x2 = k[base+1];
    k[base]   = x1*cs - x2*sn;
    k[base+1] = x1*sn + x2*cs;
}

// ---------------- causal flash attention (fp32), 64-row Q tile, 32-row K tile --------
__global__ void attn_kernel(const float* __restrict__ q, const float* __restrict__ k,
                            const float* __restrict__ v, float* __restrict__ o) {
    __shared__ float QsT[64*65];
    __shared__ float KsT[64*33];
    __shared__ float PsT[32*65];
    __shared__ float Vs [32*64];
    int tid = threadIdx.x, tx = tid & 15, ty = tid >> 4;
    int bh = blockIdx.y; int b = bh >> 4, h = bh & 15;
    int qt = blockIdx.x; int q0 = qt * 64;
    size_t tokb = (size_t)b * Sq;

    #pragma unroll
    for (int l = 0; l < 4; l++) {
        int idx = l*256 + tid; int m = idx >> 4, d4 = idx & 15;
        float4 val = *(const float4*)(q + (tokb + q0 + m) * Dq + h*HDq + d4*4);
        QsT[(d4*4+0)*65 + m] = val.x; QsT[(d4*4+1)*65 + m] = val.y;
        QsT[(d4*4+2)*65 + m] = val.z; QsT[(d4*4+3)*65 + m] = val.w;
    }
    float accO[4][4] = {};
    float mrow[4], lrow[4];
    #pragma unroll
    for (int i = 0; i < 4; i++) { mrow[i] = -1e30f; lrow[i] = 0.f; }
    __syncthreads();

    int ktmax = 2*qt + 1;
    for (int kt = 0; kt <= ktmax; kt++) {
        int k0 = kt * 32;
        #pragma unroll
        for (int l = 0; l < 2; l++) {
            int idx = l*256 + tid; int m = idx >> 4, d4 = idx & 15;
            float4 kv = *(const float4*)(k + (tokb + k0 + m) * Dq + h*HDq + d4*4);
            KsT[(d4*4+0)*33 + m] = kv.x; KsT[(d4*4+1)*33 + m] = kv.y;
            KsT[(d4*4+2)*33 + m] = kv.z; KsT[(d4*4+3)*33 + m] = kv.w;
            float4 vv = *(const float4*)(v + (tokb + k0 + m) * Dq + h*HDq + d4*4);
            *(float4*)(&Vs[m*64 + d4*4]) = vv;
        }
        __syncthreads();

        float s[4][2] = {};
        #pragma unroll 16
        for (int d = 0; d < 64; d++) {
            float a0 = QsT[d*65 + ty*4+0], a1 = QsT[d*65 + ty*4+1];
            float a2 = QsT[d*65 + ty*4+2], a3 = QsT[d*65 + ty*4+3];
            float b0 = KsT[d*33 + tx*2+0], b1 = KsT[d*33 + tx*2+1];
            s[0][0] += a0*b0; s[0][1] += a0*b1;
            s[1][0] += a1*b0; s[1][1] += a1*b1;
            s[2][0] += a2*b0; s[2][1] += a2*b1;
            s[3][0] += a3*b0; s[3][1] += a3*b1;
        }
        bool domask = (kt >= 2*qt);
        #pragma unroll
        for (int i = 0; i < 4; i++)
            #pragma unroll
            for (int j = 0; j < 2; j++) {
                float val = s[i][j] * 0.125f;
                if (domask && (k0 + tx*2 + j) > (q0 + ty*4 + i)) val = -1.0e9f;
                s[i][j] = val;
            }
        #pragma unroll
        for (int i = 0; i < 4; i++) {
            float m_ = fmaxf(s[i][0], s[i][1]);
            #pragma unroll
            for (int ofs = 8; ofs; ofs >>= 1)
                m_ = fmaxf(m_, __shfl_xor_sync(0xffffffffu, m_, ofs));
            float newm = fmaxf(mrow[i], m_);
            float sum = 0.f;
            #pragma unroll
            for (int j = 0; j < 2; j++) {
                float p = __expf(s[i][j] - newm); s[i][j] = p; sum += p;
            }
            #pragma unroll
            for (int ofs = 8; ofs; ofs >>= 1)
                sum += __shfl_xor_sync(0xffffffffu, sum, ofs);
            float corr = __expf(mrow[i] - newm);
            lrow[i] = lrow[i] * corr + sum;
            mrow[i] = newm;
            #pragma unroll
            for (int c = 0; c < 4; c++) accO[i][c] *= corr;
        }
        #pragma unroll
        for (int i = 0; i < 4; i++)
            #pragma unroll
            for (int j = 0; j < 2; j++)
                PsT[(tx*2 + j)*65 + ty*4 + i] = s[i][j];
        __syncthreads();
        #pragma unroll
        for (int n = 0; n < 32; n++) {
            float p0 = PsT[n*65 + ty*4+0], p1 = PsT[n*65 + ty*4+1];
            float p2 = PsT[n*65 + ty*4+2], p3 = PsT[n*65 + ty*4+3];
            float4 vv = *(const float4*)(&Vs[n*64 + tx*4]);
            accO[0][0] += p0*vv.x; accO[0][1] += p0*vv.y; accO[0][2] += p0*vv.z; accO[0][3] += p0*vv.w;
            accO[1][0] += p1*vv.x; accO[1][1] += p1*vv.y; accO[1][2] += p1*vv.z; accO[1][3] += p1*vv.w;
            accO[2][0] += p2*vv.x; accO[2][1] += p2*vv.y; accO[2][2] += p2*vv.z; accO[2][3] += p2*vv.w;
            accO[3][0] += p3*vv.x; accO[3][1] += p3*vv.y; accO[3][2] += p3*vv.z; accO[3][3] += p3*vv.w;
        }
        __syncthreads();
    }
    #pragma unroll
    for (int i = 0; i < 4; i++) {
        float invl = 1.f / lrow[i];
        float4 ov = make_float4(accO[i][0]*invl, accO[i][1]*invl,
                                accO[i][2]*invl, accO[i][3]*invl);
        *(float4*)(o + (tokb + q0 + ty*4 + i) * Dq + h*HDq + tx*4) = ov;
    }
}

// ---------------- MoE gate ----------------
__global__ void gate_kernel(const float* __restrict__ h2, const float* __restrict__ gw,
                            int* __restrict__ topi, float* __restrict__ topv,
                            int* __restrict__ cnt) {
    int t = blockIdx.x;
    __shared__ float part[128*Eq];
    __shared__ float logit[Eq];
    float acc[Eq] = {};
    const float* x = h2 + (size_t)t * Dq;
    for (int d = threadIdx.x; d < Dq; d += 128) {
        float xv = x[d];
        #pragma unroll
        for (int e = 0; e < Eq; e++) acc[e] += xv * gw[d*Eq + e];
    }
    #pragma unroll
    for (int e = 0; e < Eq; e++) part[threadIdx.x*Eq + e] = acc[e];
    __syncthreads();
    if (threadIdx.x < Eq) {
        float s = 0.f;
        for (int i = 0; i < 128; i++) s += part[i*Eq + threadIdx.x];
        logit[threadIdx.x] = s;
    }
    __syncthreads();
    if (threadIdx.x == 0) {
        float mx = logit[0];
        #pragma unroll
        for (int e = 1; e < Eq; e++) mx = fmaxf(mx, logit[e]);
        float p[Eq];
        #pragma unroll
        for (int e = 0; e < Eq; e++) p[e] = expf(logit[e] - mx);
        int i0 = 0;
        #pragma unroll
        for (int e = 1; e < Eq; e++) if (p[e] > p[i0]) i0 = e;
        int i1 = (i0 == 0) ? 1 : 0;
        #pragma unroll
        for (int e = 0; e < Eq; e++) if (e != i0 && p[e] > p[i1]) i1 = e;
        float inv = 1.f / (p[i0] + p[i1]);
        topi[t*2]   = i0; topi[t*2+1] = i1;
        topv[t*2]   = p[i0]*inv; topv[t*2+1] = p[i1]*inv;
        atomicAdd(&cnt[i0], 1);
        atomicAdd(&cnt[i1], 1);
    }
}

__global__ void zero_cnt_kernel(int* cnt) {
    if (threadIdx.x < Eq) cnt[threadIdx.x] = 0;
}

__global__ void offsets_kernel(const int* __restrict__ cnt, int* __restrict__ off) {
    if (threadIdx.x == 0) {
        int acc = 0; off[0] = 0;
        for (int e = 0; e < Eq; e++) { acc += (cnt[e] + 127) & ~127; off[e+1] = acc; }
    }
}

// deterministic scatter
__global__ void scatter_kernel(const int* __restrict__ topi, const int* __restrict__ off,
                               int* __restrict__ rowtok, int* __restrict__ rowpos) {
    int e = blockIdx.x;
    __shared__ int sflag[256];
    __shared__ int sbase;
    int base = off[e];
    if (threadIdx.x == 0) sbase = 0;
    __syncthreads();
    for (int c = 0; c < Tq*Kq; c += 256) {
        int a = c + threadIdx.x;
        int f = (topi[a] == e) ? 1 : 0;
        sflag[threadIdx.x] = f;
        __syncthreads();
        for (int ofs = 1; ofs < 256; ofs <<= 1) {
            int v = (threadIdx.x >= ofs) ? sflag[threadIdx.x - ofs] : 0;
            __syncthreads();
            sflag[threadIdx.x] += v;
            __syncthreads();
        }
        if (f) {
            int pos = base + sbase + sflag[threadIdx.x] - 1;
            rowtok[pos] = a >> 1;
            rowpos[a] = pos;
        }
        __syncthreads();
        if (threadIdx.x == 0) sbase += sflag[255];
        __syncthreads();
    }
    for (int p = base + sbase + threadIdx.x; p < off[e+1]; p += 256) rowtok[p] = -1;
}

// ---------------- MoE up (tf32 mma): hidden = silu(Xg@w1[e]) * (Xg@w3[e]) ----------------
// grid = (Fq/64, RCAP/128), block 256. Warp tile 32x32, dual B.
__global__ void __launch_bounds__(256) moe_up_tf32(
        const float* __restrict__ h2, const float* __restrict__ w1,
        const float* __restrict__ w3, const int* __restrict__ off,
        const int* __restrict__ rowtok, float* __restrict__ hidden) {
    __shared__ uint32_t As [128][36];
    __shared__ uint32_t B1s[32][72];
    __shared__ uint32_t B3s[32][72];
    __shared__ int stok[128];
    __shared__ int soff[Eq+1];
    int tid = threadIdx.x, lane = tid & 31, wid = tid >> 5;
    if (tid <= Eq) soff[tid] = off[tid];
    __syncthreads();
    int r0 = blockIdx.y * 128;
    if (r0 >= soff[Eq]) return;
    int e = 0;
    #pragma unroll
    for (int i = 0; i < Eq; i++) if (r0 >= soff[i+1]) e = i + 1;
    if (tid < 128) stok[tid] = rowtok[r0 + tid];
    __syncthreads();
    const float* B1 = w1 + (size_t)e * Dq * Fq;
    const float* B3 = w3 + (size_t)e * Dq * Fq;
    int n0 = blockIdx.x * 64;
    int wm = (wid & 3) * 32, wn = (wid >> 2) * 32;
    int lr = lane >> 2, lc = lane & 3;
    float acc1[2][4][4] = {}, acc3[2][4][4] = {};

    for (int k0 = 0; k0 < Dq; k0 += 32) {
        #pragma unroll
        for (int p = 0; p < 4; p++) {
            int idx = p * 256 + tid; int m = idx >> 3, kc = idx & 7;
            int tok = stok[m];
            float4 v = make_float4(0.f, 0.f, 0.f, 0.f);
            if (tok >= 0) v = *(const float4*)(h2 + (size_t)tok * Dq + k0 + kc * 4);
            As[m][kc*4+0] = f2tf(v.x); As[m][kc*4+1] = f2tf(v.y);
            As[m][kc*4+2] = f2tf(v.z); As[m][kc*4+3] = f2tf(v.w);
        }
        #pragma unroll
        for (int p = 0; p < 2; p++) {
            int idx = p * 256 + tid; int k = idx >> 4, nc = idx & 15;
            float4 v1 = *(const float4*)(B1 + (size_t)(k0 + k) * Fq + n0 + nc * 4);
            B1s[k][nc*4+0] = f2tf(v1.x); B1s[k][nc*4+1] = f2tf(v1.y);
            B1s[k][nc*4+2] = f2tf(v1.z); B1s[k][nc*4+3] = f2tf(v1.w);
            float4 v3 = *(const float4*)(B3 + (size_t)(k0 + k) * Fq + n0 + nc * 4);
            B3s[k][nc*4+0] = f2tf(v3.x); B3s[k][nc*4+1] = f2tf(v3.y);
            B3s[k][nc*4+2] = f2tf(v3.z); B3s[k][nc*4+3] = f2tf(v3.w);
        }
        __syncthreads();
        #pragma unroll
        for (int kk = 0; kk < 4; kk++) {
            int kb = kk * 8;
            uint32_t a[2][4];
            #pragma unroll
            for (int mi = 0; mi < 2; mi++) {
                int rb = wm + mi * 16;
                a[mi][0] = As[rb + lr     ][kb + lc    ];
                a[mi][1] = As[rb + lr + 8 ][kb + lc    ];
                a[mi][2] = As[rb + lr     ][kb + lc + 4];
                a[mi][3] = As[rb + lr + 8 ][kb + lc + 4];
            }
            #pragma unroll
            for (int ni = 0; ni < 4; ni++) {
                int nb = wn + ni * 8;
                uint32_t b10 = B1s[kb + lc    ][nb + lr];
                uint32_t b11 = B1s[kb + lc + 4][nb + lr];
                uint32_t b30 = B3s[kb + lc    ][nb + lr];
                uint32_t b31 = B3s[kb + lc + 4][nb + lr];
                mma_tf32(acc1[0][ni], a[0][0], a[0][1], a[0][2], a[0][3], b10, b11);
                mma_tf32(acc1[1][ni], a[1][0], a[1][1], a[1][2], a[1][3], b10, b11);
                mma_tf32(acc3[0][ni], a[0][0], a[0][1], a[0][2], a[0][3], b30, b31);
                mma_tf32(acc3[1][ni], a[1][0], a[1][1], a[1][2], a[1][3], b30, b31);
            }
        }
        __syncthreads();
    }
    #pragma unroll
    for (int mi = 0; mi < 2; mi++) {
        int row = r0 + wm + mi * 16 + lr;
        #pragma unroll
        for (int ni = 0; ni < 4; ni++) {
            int col = n0 + wn + ni * 8 + lc * 2;
            #pragma unroll
            for (int half = 0; half < 2; half++) {
                float u0 = acc1[mi][ni][half*2+0], u1 = acc1[mi][ni][half*2+1];
                float g0 = u0 / (1.f + expf(-u0));
                float g1 = u1 / (1.f + expf(-u1));
                float2 hv = make_float2(g0 * acc3[mi][ni][half*2+0],
                                        g1 * acc3[mi][ni][half*2+1]);
                *(float2*)(hidden + (size_t)(row + half*8) * Fq + col) = hv;
            }
        }
    }
}

// ---------------- MoE down (tf32 mma): y = hidden @ w2[e] ----------------
// grid = (Dq/128, RCAP/128), block 256.
__global__ void __launch_bounds__(256) moe_down_tf32(
        const float* __restrict__ hidden, const float* __restrict__ w2,
        const int* __restrict__ off, float* __restrict__ y) {
    __shared__ uint32_t As[128][36];
    __shared__ uint32_t Bs[32][136];
    __shared__ int soff[Eq+1];
    int tid = threadIdx.x, lane = tid & 31, wid = tid >> 5;
    if (tid <= Eq) soff[tid] = off[tid];
    __syncthreads();
    int r0 = blockIdx.y * 128;
    if (r0 >= soff[Eq]) return;
    int e = 0;
    #pragma unroll
    for (int i = 0; i < Eq; i++) if (r0 >= soff[i+1]) e = i + 1;
    const float* Bm = w2 + (size_t)e * Fq * Dq;
    int n0 = blockIdx.x * 128;
    int wm = (wid & 3) * 32, wn = (wid >> 2) * 64;
    int lr = lane >> 2, lc = lane & 3;
    float acc[2][8][4] = {};

    for (int k0 = 0; k0 < Fq; k0 += 32) {
        #pragma unroll
        for (int p = 0; p < 4; p++) {
            int idx = p * 256 + tid; int m = idx >> 3, kc = idx & 7;
            float4 v = *(const float4*)(hidden + (size_t)(r0 + m) * Fq + k0 + kc * 4);
            As[m][kc*4+0] = f2tf(v.x); As[m][kc*4+1] = f2tf(v.y);
            As[m][kc*4+2] = f2tf(v.z); As[m][kc*4+3] = f2tf(v.w);
        }
        #pragma unroll
        for (int p = 0; p < 4; p++) {
            int idx = p * 256 + tid; int k = idx >> 5, nc = idx & 31;
            float4 v = *(const float4*)(Bm + (size_t)(k0 + k) * Dq + n0 + nc * 4);
            Bs[k][nc*4+0] = f2tf(v.x); Bs[k][nc*4+1] = f2tf(v.y);
            Bs[k][nc*4+2] = f2tf(v.z); Bs[k][nc*4+3] = f2tf(v.w);
        }
        __syncthreads();
        #pragma unroll
        for (int kk = 0; kk < 4; kk++) {
            int kb = kk * 8;
            uint32_t a[2][4];
            #pragma unroll
            for (int mi = 0; mi < 2; mi++) {
                int rb = wm + mi * 16;
                a[mi][0] = As[rb + lr     ][kb + lc    ];
                a[mi][1] = As[rb + lr + 8 ][kb + lc    ];
                a[mi][2] = As[rb + lr     ][kb + lc + 4];
                a[mi][3] = As[rb + lr + 8 ][kb + lc + 4];
            }
            #pragma unroll
            for (int ni = 0; ni < 8; ni++) {
                int nb = wn + ni * 8;
                uint32_t b0 = Bs[kb + lc    ][nb + lr];
                uint32_t b1 = Bs[kb + lc + 4][nb + lr];
                mma_tf32(acc[0][ni], a[0][0], a[0][1], a[0][2], a[0][3], b0, b1);
                mma_tf32(acc[1][ni], a[1][0], a[1][1], a[1][2], a[1][3], b0, b1);
            }
        }
        __syncthreads();
    }
    #pragma unroll
    for (int mi = 0; mi < 2; mi++) {
        int row = r0 + wm + mi * 16 + lr;
        #pragma unroll
        for (int ni = 0; ni < 8; ni++) {
            int col = n0 + wn + ni * 8 + lc * 2;
            *(float2*)(y + (size_t)row * Dq + col) =
                make_float2(acc[mi][ni][0], acc[mi][ni][1]);
            *(float2*)(y + (size_t)(row + 8) * Dq + col) =
                make_float2(acc[mi][ni][2], acc[mi][ni][3]);
        }
    }
}

// ---------------- combine: out = h + w0*y[p0] + w1*y[p1] ----------------
__global__ void combine_kernel(const float* __restrict__ h, const float* __restrict__ y,
                               const int* __restrict__ rowpos, const float* __restrict__ topv,
                               float* __restrict__ out) {
    int idx = blockIdx.x * 256 + threadIdx.x;   // over Tq*Dq
    int t = idx >> 10;
    int d = idx & 1023;
    int p0 = rowpos[t*2], p1 = rowpos[t*2+1];
    float w0 = topv[t*2], w1 = topv[t*2+1];
    out[idx] = h[idx] + w0 * y[(size_t)p0 * Dq + d] + w1 * y[(size_t)p1 * Dq + d];
}

// ---------------- launch ----------------
extern "C" void kernel_launch(void* const* d_in, const int* in_sizes, int n_in,
                              void* d_out, int out_size) {
    const float* x    = (const float*)d_in[0];
    const int*   pos  = (const int*)  d_in[1];
    const float* ln1  = (const float*)d_in[2];
    const float* ln2  = (const float*)d_in[3];
    const float* wq   = (const float*)d_in[4];
    const float* wk   = (const float*)d_in[5];
    const float* wv   = (const float*)d_in[6];
    const float* wo   = (const float*)d_in[7];
    const float* gw   = (const float*)d_in[8];
    const float* w1   = (const float*)d_in[9];
    const float* w3   = (const float*)d_in[10];
    const float* w2   = (const float*)d_in[11];
    float* out = (float*)d_out;

    float *h1, *qb, *kb, *vb, *attnb, *hb, *h2b, *hid, *yb, *topv;
    int *topi, *cnt, *off, *rowtok, *rowpos;
    cudaGetSymbolAddress((void**)&h1,     g_h1);
    cudaGetSymbolAddress((void**)&qb,     g_qb);
    cudaGetSymbolAddress((void**)&kb,     g_kb);
    cudaGetSymbolAddress((void**)&vb,     g_vb);
    cudaGetSymbolAddress((void**)&attnb,  g_attn);
    cudaGetSymbolAddress((void**)&hb,     g_h);
    cudaGetSymbolAddress((void**)&h2b,    g_h2);
    cudaGetSymbolAddress((void**)&hid,    g_hidden);
    cudaGetSymbolAddress((void**)&yb,     g_y);
    cudaGetSymbolAddress((void**)&topv,   g_topv);
    cudaGetSymbolAddress((void**)&topi,   g_topi);
    cudaGetSymbolAddress((void**)&cnt,    g_cnt);
    cudaGetSymbolAddress((void**)&off,    g_off);
    cudaGetSymbolAddress((void**)&rowtok, g_rowtok);
    cudaGetSymbolAddress((void**)&rowpos, g_rowpos);

    dim3 gproj(Dq/128, Tq/128);   // (8, 32)

    rmsnorm_kernel<<<Tq, 256>>>(x, ln1, h1);
    gemm_tf32<<<gproj, 256>>>(h1, wq, nullptr, qb, Dq, Dq);
    gemm_tf32<<<gproj, 256>>>(h1, wk, nullptr, kb, Dq, Dq);
    gemm_tf32<<<gproj, 256>>>(h1, wv, nullptr, vb, Dq, Dq);
    rope_kernel<<<(Tq*Hq*32)/256, 256>>>(qb, kb, pos);
    attn_kernel<<<dim3(Sq/64, Bq*Hq), 256>>>(qb, kb, vb, attnb);
    gemm_tf32<<<gproj, 256>>>(attnb, wo, x, hb, Dq, Dq);
    rmsnorm_kernel<<<Tq, 256>>>(hb, ln2, h2b);

    zero_cnt_kernel<<<1, 32>>>(cnt);
    gate_kernel<<<Tq, 128>>>(h2b, gw, topi, topv, cnt);
    offsets_kernel<<<1, 32>>>(cnt, off);
    scatter_kernel<<<Eq, 256>>>(topi, off, rowtok, rowpos);
    moe_up_tf32<<<dim3(Fq/64, RCAP/128), 256>>>(h2b, w1, w3, off, rowtok, hid);
    moe_down_tf32<<<dim3(Dq/128, RCAP/128), 256>>>(hid, w2, off, yb);
    combine_kernel<<<(Tq*Dq)/256, 256>>>(hb, yb, rowpos, topv, out);
}

// round 15
// speedup vs baseline: 2.5662x; 1.2103x over previous
#include <cuda_runtime.h>
#include <math.h>
#include <stdint.h>

// ---------------- problem constants ----------------
#define Bq   2
#define Sq   2048
#define Dq   1024
#define Hq   16
#define HDq  64
#define Fq   4096
#define Eq   8
#define Kq   2
#define Tq   (Bq*Sq)          // 4096 tokens
#define RCAP 9216             // 8192 assignments + 8*128 padding, /128

// smem word geometry (32-bit words)
#define A_STR 36
#define A_SZ  (128*A_STR)     // 4608 words per stage
#define B_STR 136
#define B_SZ  (32*B_STR)      // 4352 words per stage
#define BU_STR 72
#define BU_SZ (32*BU_STR)     // 2304 words per stage (moe_up half-width B)

#define SMEM_GEMM  ((2*A_SZ + 2*B_SZ)*4)            // 71680 B
#define SMEM_UP    ((2*A_SZ + 4*BU_SZ)*4)           // 73728 B

// ---------------- static device scratch ----------------
__device__ float g_h1[Tq*Dq];
__device__ float g_qb[Tq*Dq];
__device__ float g_kb[Tq*Dq];
__device__ float g_vb[Tq*Dq];
__device__ float g_attn[Tq*Dq];
__device__ float g_h[Tq*Dq];
__device__ float g_h2[Tq*Dq];
__device__ int   g_topi[Tq*Kq];
__device__ float g_topv[Tq*Kq];
__device__ int   g_cnt[Eq];
__device__ int   g_off[Eq+1];
__device__ int   g_rowtok[RCAP];
__device__ int   g_rowpos[Tq*Kq];
__device__ float g_hidden[(size_t)RCAP*Fq];
__device__ float g_y[(size_t)RCAP*Dq];

// ---------------- mma / cp.async helpers ----------------
__device__ __forceinline__ void mma_tf32(float* c,
        uint32_t a0, uint32_t a1, uint32_t a2, uint32_t a3,
        uint32_t b0, uint32_t b1) {
    asm volatile(
        "mma.sync.aligned.m16n8k8.row.col.f32.tf32.tf32.f32 "
        "{%0,%1,%2,%3}, {%4,%5,%6,%7}, {%8,%9}, {%0,%1,%2,%3};\n"
        : "+f"(c[0]), "+f"(c[1]), "+f"(c[2]), "+f"(c[3])
        : "r"(a0), "r"(a1), "r"(a2), "r"(a3), "r"(b0), "r"(b1));
}
__device__ __forceinline__ void cpa16(uint32_t dst, const void* src) {
    asm volatile("cp.async.cg.shared.global [%0], [%1], 16;" :: "r"(dst), "l"(src));
}
__device__ __forceinline__ void cpa16z(uint32_t dst, const void* src, int src_sz) {
    asm volatile("cp.async.cg.shared.global [%0], [%1], 16, %2;"
                 :: "r"(dst), "l"(src), "r"(src_sz));
}
__device__ __forceinline__ void cpa_commit() {
    asm volatile("cp.async.commit_group;");
}
__device__ __forceinline__ void cpa_wait1() {
    asm volatile("cp.async.wait_group 1;");
}
__device__ __forceinline__ void cpa_wait0() {
    asm volatile("cp.async.wait_group 0;");
}

// ---------------- rmsnorm ----------------
__global__ void rmsnorm_kernel(const float* __restrict__ x,
                               const float* __restrict__ w,
                               float* __restrict__ out) {
    int t = blockIdx.x;
    const float* xr = x + (size_t)t * Dq;
    __shared__ float red[256];
    float s = 0.f;
    for (int d = threadIdx.x; d < Dq; d += 256) { float v = xr[d]; s += v*v; }
    red[threadIdx.x] = s; __syncthreads();
    for (int ofs = 128; ofs > 0; ofs >>= 1) {
        if (threadIdx.x < ofs) red[threadIdx.x] += red[threadIdx.x + ofs];
        __syncthreads();
    }
    float r = rsqrtf(red[0] / (float)Dq + 1e-5f);
    float* o = out + (size_t)t * Dq;
    for (int d = threadIdx.x; d < Dq; d += 256) o[d] = xr[d] * r * w[d];
}

// ---------------- tf32 GEMM 128x128x32, cp.async double-buffered -------------
// C[M x N] = A @ B (+Res). grid (N/128, M/128), block 256, dyn smem SMEM_GEMM.
__global__ void __launch_bounds__(256) gemm_tf32(
        const float* __restrict__ A, const float* __restrict__ B,
        const float* __restrict__ Res, float* __restrict__ C,
        int N, int Kd) {
    extern __shared__ uint32_t sm[];
    uint32_t sb = (uint32_t)__cvta_generic_to_shared(sm);
    int tid = threadIdx.x, lane = tid & 31, wid = tid >> 5;
    int wm = (wid & 3) * 32, wn = (wid >> 2) * 64;
    int m0 = blockIdx.y * 128, n0 = blockIdx.x * 128;
    int lr = lane >> 2, lc = lane & 3;
    float acc[2][8][4] = {};

    int am = tid >> 3, akc = tid & 7;          // A: 4 chunks/thread, m += 32/p
    int bk = tid >> 5, bnc = tid & 31;         // B: 4 chunks/thread, k += 8/p

    const int KT = Kd >> 5;
    #pragma unroll 1
    for (int kt = 0; kt < KT + 1; kt++) {
        if (kt < KT) {
            int s = kt & 1, k0 = kt << 5;
            #pragma unroll
            for (int p = 0; p < 4; p++) {
                int m = am + p * 32;
                cpa16(sb + (uint32_t)(s*A_SZ + m*A_STR + akc*4)*4,
                      A + (size_t)(m0 + m) * Kd + k0 + akc*4);
            }
            #pragma unroll
            for (int p = 0; p < 4; p++) {
                int k = bk + p * 8;
                cpa16(sb + (uint32_t)(2*A_SZ + s*B_SZ + k*B_STR + bnc*4)*4,
                      B + (size_t)(k0 + k) * N + n0 + bnc*4);
            }
            cpa_commit();
        }
        if (kt == 0) continue;
        if (kt < KT) cpa_wait1(); else cpa_wait0();
        __syncthreads();
        int s = (kt - 1) & 1;
        const uint32_t* Asm = sm + s*A_SZ;
        const uint32_t* Bsm = sm + 2*A_SZ + s*B_SZ;
        #pragma unroll
        for (int kk = 0; kk < 4; kk++) {
            int kb = kk * 8;
            uint32_t a[2][4];
            #pragma unroll
            for (int mi = 0; mi < 2; mi++) {
                int rb = wm + mi * 16;
                a[mi][0] = Asm[(rb + lr     )*A_STR + kb + lc    ];
                a[mi][1] = Asm[(rb + lr + 8 )*A_STR + kb + lc    ];
                a[mi][2] = Asm[(rb + lr     )*A_STR + kb + lc + 4];
                a[mi][3] = Asm[(rb + lr + 8 )*A_STR + kb + lc + 4];
            }
            #pragma unroll
            for (int ni = 0; ni < 8; ni++) {
                int nb = wn + ni * 8;
                uint32_t b0 = Bsm[(kb + lc    )*B_STR + nb + lr];
                uint32_t b1 = Bsm[(kb + lc + 4)*B_STR + nb + lr];
                mma_tf32(acc[0][ni], a[0][0], a[0][1], a[0][2], a[0][3], b0, b1);
                mma_tf32(acc[1][ni], a[1][0], a[1][1], a[1][2], a[1][3], b0, b1);
            }
        }
        __syncthreads();
    }
    #pragma unroll
    for (int mi = 0; mi < 2; mi++) {
        int r0 = m0 + wm + mi * 16 + lr;
        #pragma unroll
        for (int ni = 0; ni < 8; ni++) {
            int c0 = n0 + wn + ni * 8 + lc * 2;
            float2 v0 = make_float2(acc[mi][ni][0], acc[mi][ni][1]);
            float2 v1 = make_float2(acc[mi][ni][2], acc[mi][ni][3]);
            if (Res) {
                const float2 r0v = *(const float2*)(Res + (size_t)r0 * N + c0);
                const float2 r1v = *(const float2*)(Res + (size_t)(r0+8) * N + c0);
                v0.x += r0v.x; v0.y += r0v.y; v1.x += r1v.x; v1.y += r1v.y;
            }
            *(float2*)(C + (size_t)r0 * N + c0) = v0;
            *(float2*)(C + (size_t)(r0 + 8) * N + c0) = v1;
        }
    }
}

// ---------------- RoPE (in place on q,k) ----------------
__global__ void rope_kernel(float* __restrict__ q, float* __restrict__ k,
                            const int* __restrict__ pos) {
    int idx = blockIdx.x * 256 + threadIdx.x;       // over Tq*Hq*32
    if (idx >= Tq*Hq*32) return;
    int i = idx & 31;
    int h = (idx >> 5) & (Hq - 1);
    int t = idx >> 9;
    float inv = expf(-(float)i * (9.2103403719761836f / 32.f));
    float ang = (float)pos[t] * inv;
    float sn, cs; sincosf(ang, &sn, &cs);
    size_t base = (size_t)t * Dq + h * HDq + 2 * i;
    float x1 = q[base], x2 = q[base+1];
    q[base]   = x1*cs - x2*sn;
    q[base+1] = x1*sn + x2*cs;
    x1 = k[base]; x2 = k[base+1];
    k[base]   = x1*cs - x2*sn;
    k[base+1] = x1*sn + x2*cs;
}

// ---------------- causal flash attention (fp32) ----------------
__global__ void attn_kernel(const float* __restrict__ q, const float* __restrict__ k,
                            const float* __restrict__ v, float* __restrict__ o) {
    __shared__ float QsT[64*65];
    __shared__ float KsT[64*33];
    __shared__ float PsT[32*65];
    __shared__ float Vs [32*64];
    int tid = threadIdx.x, tx = tid & 15, ty = tid >> 4;
    int bh = blockIdx.y; int b = bh >> 4, h = bh & 15;
    int qt = blockIdx.x; int q0 = qt * 64;
    size_t tokb = (size_t)b * Sq;

    #pragma unroll
    for (int l = 0; l < 4; l++) {
        int idx = l*256 + tid; int m = idx >> 4, d4 = idx & 15;
        float4 val = *(const float4*)(q + (tokb + q0 + m) * Dq + h*HDq + d4*4);
        QsT[(d4*4+0)*65 + m] = val.x; QsT[(d4*4+1)*65 + m] = val.y;
        QsT[(d4*4+2)*65 + m] = val.z; QsT[(d4*4+3)*65 + m] = val.w;
    }
    float accO[4][4] = {};
    float mrow[4], lrow[4];
    #pragma unroll
    for (int i = 0; i < 4; i++) { mrow[i] = -1e30f; lrow[i] = 0.f; }
    __syncthreads();

    int ktmax = 2*qt + 1;
    for (int kt = 0; kt <= ktmax; kt++) {
        int k0 = kt * 32;
        #pragma unroll
        for (int l = 0; l < 2; l++) {
            int idx = l*256 + tid; int m = idx >> 4, d4 = idx & 15;
            float4 kv = *(const float4*)(k + (tokb + k0 + m) * Dq + h*HDq + d4*4);
            KsT[(d4*4+0)*33 + m] = kv.x; KsT[(d4*4+1)*33 + m] = kv.y;
            KsT[(d4*4+2)*33 + m] = kv.z; KsT[(d4*4+3)*33 + m] = kv.w;
            float4 vv = *(const float4*)(v + (tokb + k0 + m) * Dq + h*HDq + d4*4);
            *(float4*)(&Vs[m*64 + d4*4]) = vv;
        }
        __syncthreads();

        float s[4][2] = {};
        #pragma unroll 16
        for (int d = 0; d < 64; d++) {
            float a0 = QsT[d*65 + ty*4+0], a1 = QsT[d*65 + ty*4+1];
            float a2 = QsT[d*65 + ty*4+2], a3 = QsT[d*65 + ty*4+3];
            float b0 = KsT[d*33 + tx*2+0], b1 = KsT[d*33 + tx*2+1];
            s[0][0] += a0*b0; s[0][1] += a0*b1;
            s[1][0] += a1*b0; s[1][1] += a1*b1;
            s[2][0] += a2*b0; s[2][1] += a2*b1;
            s[3][0] += a3*b0; s[3][1] += a3*b1;
        }
        bool domask = (kt >= 2*qt);
        #pragma unroll
        for (int i = 0; i < 4; i++)
            #pragma unroll
            for (int j = 0; j < 2; j++) {
                float val = s[i][j] * 0.125f;
                if (domask && (k0 + tx*2 + j) > (q0 + ty*4 + i)) val = -1.0e9f;
                s[i][j] = val;
            }
        #pragma unroll
        for (int i = 0; i < 4; i++) {
            float m_ = fmaxf(s[i][0], s[i][1]);
            #pragma unroll
            for (int ofs = 8; ofs; ofs >>= 1)
                m_ = fmaxf(m_, __shfl_xor_sync(0xffffffffu, m_, ofs));
            float newm = fmaxf(mrow[i], m_);
            float sum = 0.f;
            #pragma unroll
            for (int j = 0; j < 2; j++) {
                float p = __expf(s[i][j] - newm); s[i][j] = p; sum += p;
            }
            #pragma unroll
            for (int ofs = 8; ofs; ofs >>= 1)
                sum += __shfl_xor_sync(0xffffffffu, sum, ofs);
            float corr = __expf(mrow[i] - newm);
            lrow[i] = lrow[i] * corr + sum;
            mrow[i] = newm;
            #pragma unroll
            for (int c = 0; c < 4; c++) accO[i][c] *= corr;
        }
        #pragma unroll
        for (int i = 0; i < 4; i++)
            #pragma unroll
            for (int j = 0; j < 2; j++)
                PsT[(tx*2 + j)*65 + ty*4 + i] = s[i][j];
        __syncthreads();
        #pragma unroll
        for (int n = 0; n < 32; n++) {
            float p0 = PsT[n*65 + ty*4+0], p1 = PsT[n*65 + ty*4+1];
            float p2 = PsT[n*65 + ty*4+2], p3 = PsT[n*65 + ty*4+3];
            float4 vv = *(const float4*)(&Vs[n*64 + tx*4]);
            accO[0][0] += p0*vv.x; accO[0][1] += p0*vv.y; accO[0][2] += p0*vv.z; accO[0][3] += p0*vv.w;
            accO[1][0] += p1*vv.x; accO[1][1] += p1*vv.y; accO[1][2] += p1*vv.z; accO[1][3] += p1*vv.w;
            accO[2][0] += p2*vv.x; accO[2][1] += p2*vv.y; accO[2][2] += p2*vv.z; accO[2][3] += p2*vv.w;
            accO[3][0] += p3*vv.x; accO[3][1] += p3*vv.y; accO[3][2] += p3*vv.z; accO[3][3] += p3*vv.w;
        }
        __syncthreads();
    }
    #pragma unroll
    for (int i = 0; i < 4; i++) {
        float invl = 1.f / lrow[i];
        float4 ov = make_float4(accO[i][0]*invl, accO[i][1]*invl,
                                accO[i][2]*invl, accO[i][3]*invl);
        *(float4*)(o + (tokb + q0 + ty*4 + i) * Dq + h*HDq + tx*4) = ov;
    }
}

// ---------------- MoE gate ----------------
__global__ void gate_kernel(const float* __restrict__ h2, const float* __restrict__ gw,
                            int* __restrict__ topi, float* __restrict__ topv,
                            int* __restrict__ cnt) {
    int t = blockIdx.x;
    __shared__ float part[128*Eq];
    __shared__ float logit[Eq];
    float acc[Eq] = {};
    const float* x = h2 + (size_t)t * Dq;
    for (int d = threadIdx.x; d < Dq; d += 128) {
        float xv = x[d];
        #pragma unroll
        for (int e = 0; e < Eq; e++) acc[e] += xv * gw[d*Eq + e];
    }
    #pragma unroll
    for (int e = 0; e < Eq; e++) part[threadIdx.x*Eq + e] = acc[e];
    __syncthreads();
    if (threadIdx.x < Eq) {
        float s = 0.f;
        for (int i = 0; i < 128; i++) s += part[i*Eq + threadIdx.x];
        logit[threadIdx.x] = s;
    }
    __syncthreads();
    if (threadIdx.x == 0) {
        float mx = logit[0];
        #pragma unroll
        for (int e = 1; e < Eq; e++) mx = fmaxf(mx, logit[e]);
        float p[Eq];
        #pragma unroll
        for (int e = 0; e < Eq; e++) p[e] = expf(logit[e] - mx);
        int i0 = 0;
        #pragma unroll
        for (int e = 1; e < Eq; e++) if (p[e] > p[i0]) i0 = e;
        int i1 = (i0 == 0) ? 1 : 0;
        #pragma unroll
        for (int e = 0; e < Eq; e++) if (e != i0 && p[e] > p[i1]) i1 = e;
        float inv = 1.f / (p[i0] + p[i1]);
        topi[t*2]   = i0; topi[t*2+1] = i1;
        topv[t*2]   = p[i0]*inv; topv[t*2+1] = p[i1]*inv;
        atomicAdd(&cnt[i0], 1);
        atomicAdd(&cnt[i1], 1);
    }
}

__global__ void zero_cnt_kernel(int* cnt) {
    if (threadIdx.x < Eq) cnt[threadIdx.x] = 0;
}

__global__ void offsets_kernel(const int* __restrict__ cnt, int* __restrict__ off) {
    if (threadIdx.x == 0) {
        int acc = 0; off[0] = 0;
        for (int e = 0; e < Eq; e++) { acc += (cnt[e] + 127) & ~127; off[e+1] = acc; }
    }
}

// deterministic scatter
__global__ void scatter_kernel(const int* __restrict__ topi, const int* __restrict__ off,
                               int* __restrict__ rowtok, int* __restrict__ rowpos) {
    int e = blockIdx.x;
    __shared__ int sflag[256];
    __shared__ int sbase;
    int base = off[e];
    if (threadIdx.x == 0) sbase = 0;
    __syncthreads();
    for (int c = 0; c < Tq*Kq; c += 256) {
        int a = c + threadIdx.x;
        int f = (topi[a] == e) ? 1 : 0;
        sflag[threadIdx.x] = f;
        __syncthreads();
        for (int ofs = 1; ofs < 256; ofs <<= 1) {
            int v = (threadIdx.x >= ofs) ? sflag[threadIdx.x - ofs] : 0;
            __syncthreads();
            sflag[threadIdx.x] += v;
            __syncthreads();
        }
        if (f) {
            int pos = base + sbase + sflag[threadIdx.x] - 1;
            rowtok[pos] = a >> 1;
            rowpos[a] = pos;
        }
        __syncthreads();
        if (threadIdx.x == 0) sbase += sflag[255];
        __syncthreads();
    }
    for (int p = base + sbase + threadIdx.x; p < off[e+1]; p += 256) rowtok[p] = -1;
}

// ---------------- MoE up (tf32 mma, cp.async db): hidden = silu(Xg@w1)*(Xg@w3) -------
// grid = (Fq/64, RCAP/128), block 256, dyn smem SMEM_UP.
__global__ void __launch_bounds__(256) moe_up_tf32(
        const float* __restrict__ h2, const float* __restrict__ w1,
        const float* __restrict__ w3, const int* __restrict__ off,
        const int* __restrict__ rowtok, float* __restrict__ hidden) {
    extern __shared__ uint32_t sm[];
    uint32_t sb = (uint32_t)__cvta_generic_to_shared(sm);
    __shared__ int stok[128];
    __shared__ int soff[Eq+1];
    int tid = threadIdx.x, lane = tid & 31, wid = tid >> 5;
    if (tid <= Eq) soff[tid] = off[tid];
    __syncthreads();
    int r0 = blockIdx.y * 128;
    if (r0 >= soff[Eq]) return;
    int e = 0;
    #pragma unroll
    for (int i = 0; i < Eq; i++) if (r0 >= soff[i+1]) e = i + 1;
    if (tid < 128) stok[tid] = rowtok[r0 + tid];
    __syncthreads();
    const float* B1 = w1 + (size_t)e * Dq * Fq;
    const float* B3 = w3 + (size_t)e * Dq * Fq;
    int n0 = blockIdx.x * 64;
    int wm = (wid & 3) * 32, wn = (wid >> 2) * 32;
    int lr = lane >> 2, lc = lane & 3;
    float acc1[2][4][4] = {}, acc3[2][4][4] = {};

    int am = tid >> 3, akc = tid & 7;
    int bk = tid >> 4, bnc = tid & 15;
    const int B1B = 2*A_SZ, B3B = 2*A_SZ + 2*BU_SZ;   // word bases

    const int KT = Dq >> 5;   // 32
    #pragma unroll 1
    for (int kt = 0; kt < KT + 1; kt++) {
        if (kt < KT) {
            int s = kt & 1, k0 = kt << 5;
            #pragma unroll
            for (int p = 0; p < 4; p++) {
                int m = am + p * 32;
                int tok = stok[m];
                const float* src = (tok >= 0) ?
                    h2 + (size_t)tok * Dq + k0 + akc*4 : h2;
                cpa16z(sb + (uint32_t)(s*A_SZ + m*A_STR + akc*4)*4, src,
                       (tok >= 0) ? 16 : 0);
            }
            #pragma unroll
            for (int p = 0; p < 2; p++) {
                int k = bk + p * 16;
                size_t go = (size_t)(k0 + k) * Fq + n0 + bnc*4;
                cpa16(sb + (uint32_t)(B1B + s*BU_SZ + k*BU_STR + bnc*4)*4, B1 + go);
                cpa16(sb + (uint32_t)(B3B + s*BU_SZ + k*BU_STR + bnc*4)*4, B3 + go);
            }
            cpa_commit();
        }
        if (kt == 0) continue;
        if (kt < KT) cpa_wait1(); else cpa_wait0();
        __syncthreads();
        int s = (kt - 1) & 1;
        const uint32_t* Asm  = sm + s*A_SZ;
        const uint32_t* B1sm = sm + B1B + s*BU_SZ;
        const uint32_t* B3sm = sm + B3B + s*BU_SZ;
        #pragma unroll
        for (int kk = 0; kk < 4; kk++) {
            int kb = kk * 8;
            uint32_t a[2][4];
            #pragma unroll
            for (int mi = 0; mi < 2; mi++) {
                int rb = wm + mi * 16;
                a[mi][0] = Asm[(rb + lr     )*A_STR + kb + lc    ];
                a[mi][1] = Asm[(rb + lr + 8 )*A_STR + kb + lc    ];
                a[mi][2] = Asm[(rb + lr     )*A_STR + kb + lc + 4];
                a[mi][3] = Asm[(rb + lr + 8 )*A_STR + kb + lc + 4];
            }
            #pragma unroll
            for (int ni = 0; ni < 4; ni++) {
                int nb = wn + ni * 8;
                uint32_t b10 = B1sm[(kb + lc    )*BU_STR + nb + lr];
                uint32_t b11 = B1sm[(kb + lc + 4)*BU_STR + nb + lr];
                uint32_t b30 = B3sm[(kb + lc    )*BU_STR + nb + lr];
                uint32_t b31 = B3sm[(kb + lc + 4)*BU_STR + nb + lr];
                mma_tf32(acc1[0][ni], a[0][0], a[0][1], a[0][2], a[0][3], b10, b11);
                mma_tf32(acc1[1][ni], a[1][0], a[1][1], a[1][2], a[1][3], b10, b11);
                mma_tf32(acc3[0][ni], a[0][0], a[0][1], a[0][2], a[0][3], b30, b31);
                mma_tf32(acc3[1][ni], a[1][0], a[1][1], a[1][2], a[1][3], b30, b31);
            }
        }
        __syncthreads();
    }
    #pragma unroll
    for (int mi = 0; mi < 2; mi++) {
        int row = r0 + wm + mi * 16 + lr;
        #pragma unroll
        for (int ni = 0; ni < 4; ni++) {
            int col = n0 + wn + ni * 8 + lc * 2;
            #pragma unroll
            for (int half = 0; half < 2; half++) {
                float u0 = acc1[mi][ni][half*2+0], u1 = acc1[mi][ni][half*2+1];
                float g0 = u0 / (1.f + expf(-u0));
                float g1 = u1 / (1.f + expf(-u1));
                float2 hv = make_float2(g0 * acc3[mi][ni][half*2+0],
                                        g1 * acc3[mi][ni][half*2+1]);
                *(float2*)(hidden + (size_t)(row + half*8) * Fq + col) = hv;
            }
        }
    }
}

// ---------------- MoE down (tf32 mma, cp.async db): y = hidden @ w2[e] --------------
// grid = (Dq/128, RCAP/128), block 256, dyn smem SMEM_GEMM.
__global__ void __launch_bounds__(256) moe_down_tf32(
        const float* __restrict__ hidden, const float* __restrict__ w2,
        const int* __restrict__ off, float* __restrict__ y) {
    extern __shared__ uint32_t sm[];
    uint32_t sb = (uint32_t)__cvta_generic_to_shared(sm);
    __shared__ int soff[Eq+1];
    int tid = threadIdx.x, lane = tid & 31, wid = tid >> 5;
    if (tid <= Eq) soff[tid] = off[tid];
    __syncthreads();
    int r0 = blockIdx.y * 128;
    if (r0 >= soff[Eq]) return;
    int e = 0;
    #pragma unroll
    for (int i = 0; i < Eq; i++) if (r0 >= soff[i+1]) e = i + 1;
    const float* Bm = w2 + (size_t)e * Fq * Dq;
    int n0 = blockIdx.x * 128;
    int wm = (wid & 3) * 32, wn = (wid >> 2) * 64;
    int lr = lane >> 2, lc = lane & 3;
    float acc[2][8][4] = {};

    int am = tid >> 3, akc = tid & 7;
    int bk = tid >> 5, bnc = tid & 31;

    const int KT = Fq >> 5;   // 128
    #pragma unroll 1
    for (int kt = 0; kt < KT + 1; kt++) {
        if (kt < KT) {
            int s = kt & 1, k0 = kt << 5;
            #pragma unroll
            for (int p = 0; p < 4; p++) {
                int m = am + p * 32;
                cpa16(sb + (uint32_t)(s*A_SZ + m*A_STR + akc*4)*4,
                      hidden + (size_t)(r0 + m) * Fq + k0 + akc*4);
            }
            #pragma unroll
            for (int p = 0; p < 4; p++) {
                int k = bk + p * 8;
                cpa16(sb + (uint32_t)(2*A_SZ + s*B_SZ + k*B_STR + bnc*4)*4,
                      Bm + (size_t)(k0 + k) * Dq + n0 + bnc*4);
            }
            cpa_commit();
        }
        if (kt == 0) continue;
        if (kt < KT) cpa_wait1(); else cpa_wait0();
        __syncthreads();
        int s = (kt - 1) & 1;
        const uint32_t* Asm = sm + s*A_SZ;
        const uint32_t* Bsm = sm + 2*A_SZ + s*B_SZ;
        #pragma unroll
        for (int kk = 0; kk < 4; kk++) {
            int kb = kk * 8;
            uint32_t a[2][4];
            #pragma unroll
            for (int mi = 0; mi < 2; mi++) {
                int rb = wm + mi * 16;
                a[mi][0] = Asm[(rb + lr     )*A_STR + kb + lc    ];
                a[mi][1] = Asm[(rb + lr + 8 )*A_STR + kb + lc    ];
                a[mi][2] = Asm[(rb + lr     )*A_STR + kb + lc + 4];
                a[mi][3] = Asm[(rb + lr + 8 )*A_STR + kb + lc + 4];
            }
            #pragma unroll
            for (int ni = 0; ni < 8; ni++) {
                int nb = wn + ni * 8;
                uint32_t b0 = Bsm[(kb + lc    )*B_STR + nb + lr];
                uint32_t b1 = Bsm[(kb + lc + 4)*B_STR + nb + lr];
                mma_tf32(acc[0][ni], a[0][0], a[0][1], a[0][2], a[0][3], b0, b1);
                mma_tf32(acc[1][ni], a[1][0], a[1][1], a[1][2], a[1][3], b0, b1);
            }
        }
        __syncthreads();
    }
    #pragma unroll
    for (int mi = 0; mi < 2; mi++) {
        int row = r0 + wm + mi * 16 + lr;
        #pragma unroll
        for (int ni = 0; ni < 8; ni++) {
            int col = n0 + wn + ni * 8 + lc * 2;
            *(float2*)(y + (size_t)row * Dq + col) =
                make_float2(acc[mi][ni][0], acc[mi][ni][1]);
            *(float2*)(y + (size_t)(row + 8) * Dq + col) =
                make_float2(acc[mi][ni][2], acc[mi][ni][3]);
        }
    }
}

// ---------------- combine: out = h + w0*y[p0] + w1*y[p1] ----------------
__global__ void combine_kernel(const float* __restrict__ h, const float* __restrict__ y,
                               const int* __restrict__ rowpos, const float* __restrict__ topv,
                               float* __restrict__ out) {
    int idx = blockIdx.x * 256 + threadIdx.x;   // over Tq*Dq
    int t = idx >> 10;
    int d = idx & 1023;
    int p0 = rowpos[t*2], p1 = rowpos[t*2+1];
    float w0 = topv[t*2], w1 = topv[t*2+1];
    out[idx] = h[idx] + w0 * y[(size_t)p0 * Dq + d] + w1 * y[(size_t)p1 * Dq + d];
}

// ---------------- launch ----------------
extern "C" void kernel_launch(void* const* d_in, const int* in_sizes, int n_in,
                              void* d_out, int out_size) {
    const float* x    = (const float*)d_in[0];
    const int*   pos  = (const int*)  d_in[1];
    const float* ln1  = (const float*)d_in[2];
    const float* ln2  = (const float*)d_in[3];
    const float* wq   = (const float*)d_in[4];
    const float* wk   = (const float*)d_in[5];
    const float* wv   = (const float*)d_in[6];
    const float* wo   = (const float*)d_in[7];
    const float* gw   = (const float*)d_in[8];
    const float* w1   = (const float*)d_in[9];
    const float* w3   = (const float*)d_in[10];
    const float* w2   = (const float*)d_in[11];
    float* out = (float*)d_out;

    cudaFuncSetAttribute(gemm_tf32,     cudaFuncAttributeMaxDynamicSharedMemorySize, SMEM_GEMM);
    cudaFuncSetAttribute(moe_up_tf32,   cudaFuncAttributeMaxDynamicSharedMemorySize, SMEM_UP);
    cudaFuncSetAttribute(moe_down_tf32, cudaFuncAttributeMaxDynamicSharedMemorySize, SMEM_GEMM);

    float *h1, *qb, *kb, *vb, *attnb, *hb, *h2b, *hid, *yb, *topv;
    int *topi, *cnt, *off, *rowtok, *rowpos;
    cudaGetSymbolAddress((void**)&h1,     g_h1);
    cudaGetSymbolAddress((void**)&qb,     g_qb);
    cudaGetSymbolAddress((void**)&kb,     g_kb);
    cudaGetSymbolAddress((void**)&vb,     g_vb);
    cudaGetSymbolAddress((void**)&attnb,  g_attn);
    cudaGetSymbolAddress((void**)&hb,     g_h);
    cudaGetSymbolAddress((void**)&h2b,    g_h2);
    cudaGetSymbolAddress((void**)&hid,    g_hidden);
    cudaGetSymbolAddress((void**)&yb,     g_y);
    cudaGetSymbolAddress((void**)&topv,   g_topv);
    cudaGetSymbolAddress((void**)&topi,   g_topi);
    cudaGetSymbolAddress((void**)&cnt,    g_cnt);
    cudaGetSymbolAddress((void**)&off,    g_off);
    cudaGetSymbolAddress((void**)&rowtok, g_rowtok);
    cudaGetSymbolAddress((void**)&rowpos, g_rowpos);

    dim3 gproj(Dq/128, Tq/128);   // (8, 32)

    rmsnorm_kernel<<<Tq, 256>>>(x, ln1, h1);
    gemm_tf32<<<gproj, 256, SMEM_GEMM>>>(h1, wq, nullptr, qb, Dq, Dq);
    gemm_tf32<<<gproj, 256, SMEM_GEMM>>>(h1, wk, nullptr, kb, Dq, Dq);
    gemm_tf32<<<gproj, 256, SMEM_GEMM>>>(h1, wv, nullptr, vb, Dq, Dq);
    rope_kernel<<<(Tq*Hq*32)/256, 256>>>(qb, kb, pos);
    attn_kernel<<<dim3(Sq/64, Bq*Hq), 256>>>(qb, kb, vb, attnb);
    gemm_tf32<<<gproj, 256, SMEM_GEMM>>>(attnb, wo, x, hb, Dq, Dq);
    rmsnorm_kernel<<<Tq, 256>>>(hb, ln2, h2b);

    zero_cnt_kernel<<<1, 32>>>(cnt);
    gate_kernel<<<Tq, 128>>>(h2b, gw, topi, topv, cnt);
    offsets_kernel<<<1, 32>>>(cnt, off);
    scatter_kernel<<<Eq, 256>>>(topi, off, rowtok, rowpos);
    moe_up_tf32<<<dim3(Fq/64, RCAP/128), 256, SMEM_UP>>>(h2b, w1, w3, off, rowtok, hid);
    moe_down_tf32<<<dim3(Dq/128, RCAP/128), 256, SMEM_GEMM>>>(hid, w2, off, yb);
    combine_kernel<<<(Tq*Dq)/256, 256>>>(hb, yb, rowpos, topv, out);
}

// round 16
// speedup vs baseline: 2.5664x; 1.0001x over previous
#include <cuda_runtime.h>
#include <math.h>
#include <stdint.h>

// ---------------- problem constants ----------------
#define Bq   2
#define Sq   2048
#define Dq   1024
#define Hq   16
#define HDq  64
#define Fq   4096
#define Eq   8
#define Kq   2
#define Tq   (Bq*Sq)          // 4096 tokens
#define RCAP 9216             // 8192 assignments + 8*128 padding, /128

// smem word geometry (32-bit words)
#define A_STR 36
#define A_SZ  (128*A_STR)     // 4608 words per stage
#define B_STR 136
#define B_SZ  (32*B_STR)      // 4352 words per stage
#define BU_STR 72
#define BU_SZ (32*BU_STR)     // 2304 words per stage (moe_up half-width B)

#define SMEM_GEMM  ((2*A_SZ + 2*B_SZ)*4)            // 71680 B
#define SMEM_UP    ((2*A_SZ + 4*BU_SZ)*4)           // 73728 B

// ---------------- static device scratch ----------------
__device__ float g_h1[Tq*Dq];
__device__ float g_qb[Tq*Dq];
__device__ float g_kb[Tq*Dq];
__device__ float g_vb[Tq*Dq];
__device__ float g_attn[Tq*Dq];
__device__ float g_h[Tq*Dq];
__device__ float g_h2[Tq*Dq];
__device__ int   g_topi[Tq*Kq];
__device__ float g_topv[Tq*Kq];
__device__ int   g_cnt[Eq];
__device__ int   g_off[Eq+1];
__device__ int   g_rowtok[RCAP];
__device__ int   g_rowpos[Tq*Kq];
__device__ float g_hidden[(size_t)RCAP*Fq];
__device__ float g_y[(size_t)RCAP*Dq];

// ---------------- mma / cp.async helpers ----------------
__device__ __forceinline__ void mma_tf32(float* c,
        uint32_t a0, uint32_t a1, uint32_t a2, uint32_t a3,
        uint32_t b0, uint32_t b1) {
    asm volatile(
        "mma.sync.aligned.m16n8k8.row.col.f32.tf32.tf32.f32 "
        "{%0,%1,%2,%3}, {%4,%5,%6,%7}, {%8,%9}, {%0,%1,%2,%3};\n"
        : "+f"(c[0]), "+f"(c[1]), "+f"(c[2]), "+f"(c[3])
        : "r"(a0), "r"(a1), "r"(a2), "r"(a3), "r"(b0), "r"(b1));
}
__device__ __forceinline__ void cpa16(uint32_t dst, const void* src) {
    asm volatile("cp.async.cg.shared.global [%0], [%1], 16;" :: "r"(dst), "l"(src));
}
__device__ __forceinline__ void cpa16z(uint32_t dst, const void* src, int src_sz) {
    asm volatile("cp.async.cg.shared.global [%0], [%1], 16, %2;"
                 :: "r"(dst), "l"(src), "r"(src_sz));
}
__device__ __forceinline__ void cpa_commit() {
    asm volatile("cp.async.commit_group;");
}
__device__ __forceinline__ void cpa_wait1() {
    asm volatile("cp.async.wait_group 1;");
}
__device__ __forceinline__ void cpa_wait0() {
    asm volatile("cp.async.wait_group 0;");
}

// ---------------- rmsnorm ----------------
__global__ void rmsnorm_kernel(const float* __restrict__ x,
                               const float* __restrict__ w,
                               float* __restrict__ out) {
    int t = blockIdx.x;
    const float* xr = x + (size_t)t * Dq;
    __shared__ float red[256];
    float s = 0.f;
    for (int d = threadIdx.x; d < Dq; d += 256) { float v = xr[d]; s += v*v; }
    red[threadIdx.x] = s; __syncthreads();
    for (int ofs = 128; ofs > 0; ofs >>= 1) {
        if (threadIdx.x < ofs) red[threadIdx.x] += red[threadIdx.x + ofs];
        __syncthreads();
    }
    float r = rsqrtf(red[0] / (float)Dq + 1e-5f);
    float* o = out + (size_t)t * Dq;
    for (int d = threadIdx.x; d < Dq; d += 256) o[d] = xr[d] * r * w[d];
}

// ---------------- tf32 GEMM 128x128x32, cp.async double-buffered -------------
// C[M x N] = A @ B (+Res). grid (N/128, M/128), block 256, dyn smem SMEM_GEMM.
__global__ void __launch_bounds__(256) gemm_tf32(
        const float* __restrict__ A, const float* __restrict__ B,
        const float* __restrict__ Res, float* __restrict__ C,
        int N, int Kd) {
    extern __shared__ uint32_t sm[];
    uint32_t sb = (uint32_t)__cvta_generic_to_shared(sm);
    int tid = threadIdx.x, lane = tid & 31, wid = tid >> 5;
    int wm = (wid & 3) * 32, wn = (wid >> 2) * 64;
    int m0 = blockIdx.y * 128, n0 = blockIdx.x * 128;
    int lr = lane >> 2, lc = lane & 3;
    float acc[2][8][4] = {};

    int am = tid >> 3, akc = tid & 7;          // A: 4 chunks/thread, m += 32/p
    int bk = tid >> 5, bnc = tid & 31;         // B: 4 chunks/thread, k += 8/p

    const int KT = Kd >> 5;
    #pragma unroll 1
    for (int kt = 0; kt < KT + 1; kt++) {
        if (kt < KT) {
            int s = kt & 1, k0 = kt << 5;
            #pragma unroll
            for (int p = 0; p < 4; p++) {
                int m = am + p * 32;
                cpa16(sb + (uint32_t)(s*A_SZ + m*A_STR + akc*4)*4,
                      A + (size_t)(m0 + m) * Kd + k0 + akc*4);
            }
            #pragma unroll
            for (int p = 0; p < 4; p++) {
                int k = bk + p * 8;
                cpa16(sb + (uint32_t)(2*A_SZ + s*B_SZ + k*B_STR + bnc*4)*4,
                      B + (size_t)(k0 + k) * N + n0 + bnc*4);
            }
            cpa_commit();
        }
        if (kt == 0) continue;
        if (kt < KT) cpa_wait1(); else cpa_wait0();
        __syncthreads();
        int s = (kt - 1) & 1;
        const uint32_t* Asm = sm + s*A_SZ;
        const uint32_t* Bsm = sm + 2*A_SZ + s*B_SZ;
        #pragma unroll
        for (int kk = 0; kk < 4; kk++) {
            int kb = kk * 8;
            uint32_t a[2][4];
            #pragma unroll
            for (int mi = 0; mi < 2; mi++) {
                int rb = wm + mi * 16;
                a[mi][0] = Asm[(rb + lr     )*A_STR + kb + lc    ];
                a[mi][1] = Asm[(rb + lr + 8 )*A_STR + kb + lc    ];
                a[mi][2] = Asm[(rb + lr     )*A_STR + kb + lc + 4];
                a[mi][3] = Asm[(rb + lr + 8 )*A_STR + kb + lc + 4];
            }
            #pragma unroll
            for (int ni = 0; ni < 8; ni++) {
                int nb = wn + ni * 8;
                uint32_t b0 = Bsm[(kb + lc    )*B_STR + nb + lr];
                uint32_t b1 = Bsm[(kb + lc + 4)*B_STR + nb + lr];
                mma_tf32(acc[0][ni], a[0][0], a[0][1], a[0][2], a[0][3], b0, b1);
                mma_tf32(acc[1][ni], a[1][0], a[1][1], a[1][2], a[1][3], b0, b1);
            }
        }
        __syncthreads();
    }
    #pragma unroll
    for (int mi = 0; mi < 2; mi++) {
        int r0 = m0 + wm + mi * 16 + lr;
        #pragma unroll
        for (int ni = 0; ni < 8; ni++) {
            int c0 = n0 + wn + ni * 8 + lc * 2;
            float2 v0 = make_float2(acc[mi][ni][0], acc[mi][ni][1]);
            float2 v1 = make_float2(acc[mi][ni][2], acc[mi][ni][3]);
            if (Res) {
                const float2 r0v = *(const float2*)(Res + (size_t)r0 * N + c0);
                const float2 r1v = *(const float2*)(Res + (size_t)(r0+8) * N + c0);
                v0.x += r0v.x; v0.y += r0v.y; v1.x += r1v.x; v1.y += r1v.y;
            }
            *(float2*)(C + (size_t)r0 * N + c0) = v0;
            *(float2*)(C + (size_t)(r0 + 8) * N + c0) = v1;
        }
    }
}

// ---------------- RoPE (in place on q,k) ----------------
__global__ void rope_kernel(float* __restrict__ q, float* __restrict__ k,
                            const int* __restrict__ pos) {
    int idx = blockIdx.x * 256 + threadIdx.x;       // over Tq*Hq*32
    if (idx >= Tq*Hq*32) return;
    int i = idx & 31;
    int h = (idx >> 5) & (Hq - 1);
    int t = idx >> 9;
    float inv = expf(-(float)i * (9.2103403719761836f / 32.f));
    float ang = (float)pos[t] * inv;
    float sn, cs; sincosf(ang, &sn, &cs);
    size_t base = (size_t)t * Dq + h * HDq + 2 * i;
    float x1 = q[base], x2 = q[base+1];
    q[base]   = x1*cs - x2*sn;
    q[base+1] = x1*sn + x2*cs;
    x1 = k[base]; x2 = k[base+1];
    k[base]   = x1*cs - x2*sn;
    k[base+1] = x1*sn + x2*cs;
}

// ---------------- causal flash attention (fp32) ----------------
__global__ void attn_kernel(const float* __restrict__ q, const float* __restrict__ k,
                            const float* __restrict__ v, float* __restrict__ o) {
    __shared__ float QsT[64*65];
    __shared__ float KsT[64*33];
    __shared__ float PsT[32*65];
    __shared__ float Vs [32*64];
    int tid = threadIdx.x, tx = tid & 15, ty = tid >> 4;
    int bh = blockIdx.y; int b = bh >> 4, h = bh & 15;
    int qt = blockIdx.x; int q0 = qt * 64;
    size_t tokb = (size_t)b * Sq;

    #pragma unroll
    for (int l = 0; l < 4; l++) {
        int idx = l*256 + tid; int m = idx >> 4, d4 = idx & 15;
        float4 val = *(const float4*)(q + (tokb + q0 + m) * Dq + h*HDq + d4*4);
        QsT[(d4*4+0)*65 + m] = val.x; QsT[(d4*4+1)*65 + m] = val.y;
        QsT[(d4*4+2)*65 + m] = val.z; QsT[(d4*4+3)*65 + m] = val.w;
    }
    float accO[4][4] = {};
    float mrow[4], lrow[4];
    #pragma unroll
    for (int i = 0; i < 4; i++) { mrow[i] = -1e30f; lrow[i] = 0.f; }
    __syncthreads();

    int ktmax = 2*qt + 1;
    for (int kt = 0; kt <= ktmax; kt++) {
        int k0 = kt * 32;
        #pragma unroll
        for (int l = 0; l < 2; l++) {
            int idx = l*256 + tid; int m = idx >> 4, d4 = idx & 15;
            float4 kv = *(const float4*)(k + (tokb + k0 + m) * Dq + h*HDq + d4*4);
            KsT[(d4*4+0)*33 + m] = kv.x; KsT[(d4*4+1)*33 + m] = kv.y;
            KsT[(d4*4+2)*33 + m] = kv.z; KsT[(d4*4+3)*33 + m] = kv.w;
            float4 vv = *(const float4*)(v + (tokb + k0 + m) * Dq + h*HDq + d4*4);
            *(float4*)(&Vs[m*64 + d4*4]) = vv;
        }
        __syncthreads();

        float s[4][2] = {};
        #pragma unroll 16
        for (int d = 0; d < 64; d++) {
            float a0 = QsT[d*65 + ty*4+0], a1 = QsT[d*65 + ty*4+1];
            float a2 = QsT[d*65 + ty*4+2], a3 = QsT[d*65 + ty*4+3];
            float b0 = KsT[d*33 + tx*2+0], b1 = KsT[d*33 + tx*2+1];
            s[0][0] += a0*b0; s[0][1] += a0*b1;
            s[1][0] += a1*b0; s[1][1] += a1*b1;
            s[2][0] += a2*b0; s[2][1] += a2*b1;
            s[3][0] += a3*b0; s[3][1] += a3*b1;
        }
        bool domask = (kt >= 2*qt);
        #pragma unroll
        for (int i = 0; i < 4; i++)
            #pragma unroll
            for (int j = 0; j < 2; j++) {
                float val = s[i][j] * 0.125f;
                if (domask && (k0 + tx*2 + j) > (q0 + ty*4 + i)) val = -1.0e9f;
                s[i][j] = val;
            }
        #pragma unroll
        for (int i = 0; i < 4; i++) {
            float m_ = fmaxf(s[i][0], s[i][1]);
            #pragma unroll
            for (int ofs = 8; ofs; ofs >>= 1)
                m_ = fmaxf(m_, __shfl_xor_sync(0xffffffffu, m_, ofs));
            float newm = fmaxf(mrow[i], m_);
            float sum = 0.f;
            #pragma unroll
            for (int j = 0; j < 2; j++) {
                float p = __expf(s[i][j] - newm); s[i][j] = p; sum += p;
            }
            #pragma unroll
            for (int ofs = 8; ofs; ofs >>= 1)
                sum += __shfl_xor_sync(0xffffffffu, sum, ofs);
            float corr = __expf(mrow[i] - newm);
            lrow[i] = lrow[i] * corr + sum;
            mrow[i] = newm;
            #pragma unroll
            for (int c = 0; c < 4; c++) accO[i][c] *= corr;
        }
        #pragma unroll
        for (int i = 0; i < 4; i++)
            #pragma unroll
            for (int j = 0; j < 2; j++)
                PsT[(tx*2 + j)*65 + ty*4 + i] = s[i][j];
        __syncthreads();
        #pragma unroll
        for (int n = 0; n < 32; n++) {
            float p0 = PsT[n*65 + ty*4+0], p1 = PsT[n*65 + ty*4+1];
            float p2 = PsT[n*65 + ty*4+2], p3 = PsT[n*65 + ty*4+3];
            float4 vv = *(const float4*)(&Vs[n*64 + tx*4]);
            accO[0][0] += p0*vv.x; accO[0][1] += p0*vv.y; accO[0][2] += p0*vv.z; accO[0][3] += p0*vv.w;
            accO[1][0] += p1*vv.x; accO[1][1] += p1*vv.y; accO[1][2] += p1*vv.z; accO[1][3] += p1*vv.w;
            accO[2][0] += p2*vv.x; accO[2][1] += p2*vv.y; accO[2][2] += p2*vv.z; accO[2][3] += p2*vv.w;
            accO[3][0] += p3*vv.x; accO[3][1] += p3*vv.y; accO[3][2] += p3*vv.z; accO[3][3] += p3*vv.w;
        }
        __syncthreads();
    }
    #pragma unroll
    for (int i = 0; i < 4; i++) {
        float invl = 1.f / lrow[i];
        float4 ov = make_float4(accO[i][0]*invl, accO[i][1]*invl,
                                accO[i][2]*invl, accO[i][3]*invl);
        *(float4*)(o + (tokb + q0 + ty*4 + i) * Dq + h*HDq + tx*4) = ov;
    }
}

// ---------------- MoE gate ----------------
__global__ void gate_kernel(const float* __restrict__ h2, const float* __restrict__ gw,
                            int* __restrict__ topi, float* __restrict__ topv,
                            int* __restrict__ cnt) {
    int t = blockIdx.x;
    __shared__ float part[128*Eq];
    __shared__ float logit[Eq];
    float acc[Eq] = {};
    const float* x = h2 + (size_t)t * Dq;
    for (int d = threadIdx.x; d < Dq; d += 128) {
        float xv = x[d];
        #pragma unroll
        for (int e = 0; e < Eq; e++) acc[e] += xv * gw[d*Eq + e];
    }
    #pragma unroll
    for (int e = 0; e < Eq; e++) part[threadIdx.x*Eq + e] = acc[e];
    __syncthreads();
    if (threadIdx.x < Eq) {
        float s = 0.f;
        for (int i = 0; i < 128; i++) s += part[i*Eq + threadIdx.x];
        logit[threadIdx.x] = s;
    }
    __syncthreads();
    if (threadIdx.x == 0) {
        float mx = logit[0];
        #pragma unroll
        for (int e = 1; e < Eq; e++) mx = fmaxf(mx, logit[e]);
        float p[Eq];
        #pragma unroll
        for (int e = 0; e < Eq; e++) p[e] = expf(logit[e] - mx);
        int i0 = 0;
        #pragma unroll
        for (int e = 1; e < Eq; e++) if (p[e] > p[i0]) i0 = e;
        int i1 = (i0 == 0) ? 1 : 0;
        #pragma unroll
        for (int e = 0; e < Eq; e++) if (e != i0 && p[e] > p[i1]) i1 = e;
        float inv = 1.f / (p[i0] + p[i1]);
        topi[t*2]   = i0; topi[t*2+1] = i1;
        topv[t*2]   = p[i0]*inv; topv[t*2+1] = p[i1]*inv;
        atomicAdd(&cnt[i0], 1);
        atomicAdd(&cnt[i1], 1);
    }
}

__global__ void zero_cnt_kernel(int* cnt) {
    if (threadIdx.x < Eq) cnt[threadIdx.x] = 0;
}

__global__ void offsets_kernel(const int* __restrict__ cnt, int* __restrict__ off) {
    if (threadIdx.x == 0) {
        int acc = 0; off[0] = 0;
        for (int e = 0; e < Eq; e++) { acc += (cnt[e] + 127) & ~127; off[e+1] = acc; }
    }
}

// deterministic scatter
__global__ void scatter_kernel(const int* __restrict__ topi, const int* __restrict__ off,
                               int* __restrict__ rowtok, int* __restrict__ rowpos) {
    int e = blockIdx.x;
    __shared__ int sflag[256];
    __shared__ int sbase;
    int base = off[e];
    if (threadIdx.x == 0) sbase = 0;
    __syncthreads();
    for (int c = 0; c < Tq*Kq; c += 256) {
        int a = c + threadIdx.x;
        int f = (topi[a] == e) ? 1 : 0;
        sflag[threadIdx.x] = f;
        __syncthreads();
        for (int ofs = 1; ofs < 256; ofs <<= 1) {
            int v = (threadIdx.x >= ofs) ? sflag[threadIdx.x - ofs] : 0;
            __syncthreads();
            sflag[threadIdx.x] += v;
            __syncthreads();
        }
        if (f) {
            int pos = base + sbase + sflag[threadIdx.x] - 1;
            rowtok[pos] = a >> 1;
            rowpos[a] = pos;
        }
        __syncthreads();
        if (threadIdx.x == 0) sbase += sflag[255];
        __syncthreads();
    }
    for (int p = base + sbase + threadIdx.x; p < off[e+1]; p += 256) rowtok[p] = -1;
}

// ---------------- MoE up (tf32 mma, cp.async db): hidden = silu(Xg@w1)*(Xg@w3) -------
// grid = (Fq/64, RCAP/128), block 256, dyn smem SMEM_UP.
__global__ void __launch_bounds__(256) moe_up_tf32(
        const float* __restrict__ h2, const float* __restrict__ w1,
        const float* __restrict__ w3, const int* __restrict__ off,
        const int* __restrict__ rowtok, float* __restrict__ hidden) {
    extern __shared__ uint32_t sm[];
    uint32_t sb = (uint32_t)__cvta_generic_to_shared(sm);
    __shared__ int stok[128];
    __shared__ int soff[Eq+1];
    int tid = threadIdx.x, lane = tid & 31, wid = tid >> 5;
    if (tid <= Eq) soff[tid] = off[tid];
    __syncthreads();
    int r0 = blockIdx.y * 128;
    if (r0 >= soff[Eq]) return;
    int e = 0;
    #pragma unroll
    for (int i = 0; i < Eq; i++) if (r0 >= soff[i+1]) e = i + 1;
    if (tid < 128) stok[tid] = rowtok[r0 + tid];
    __syncthreads();
    const float* B1 = w1 + (size_t)e * Dq * Fq;
    const float* B3 = w3 + (size_t)e * Dq * Fq;
    int n0 = blockIdx.x * 64;
    int wm = (wid & 3) * 32, wn = (wid >> 2) * 32;
    int lr = lane >> 2, lc = lane & 3;
    float acc1[2][4][4] = {}, acc3[2][4][4] = {};

    int am = tid >> 3, akc = tid & 7;
    int bk = tid >> 4, bnc = tid & 15;
    const int B1B = 2*A_SZ, B3B = 2*A_SZ + 2*BU_SZ;   // word bases

    const int KT = Dq >> 5;   // 32
    #pragma unroll 1
    for (int kt = 0; kt < KT + 1; kt++) {
        if (kt < KT) {
            int s = kt & 1, k0 = kt << 5;
            #pragma unroll
            for (int p = 0; p < 4; p++) {
                int m = am + p * 32;
                int tok = stok[m];
                const float* src = (tok >= 0) ?
                    h2 + (size_t)tok * Dq + k0 + akc*4 : h2;
                cpa16z(sb + (uint32_t)(s*A_SZ + m*A_STR + akc*4)*4, src,
                       (tok >= 0) ? 16 : 0);
            }
            #pragma unroll
            for (int p = 0; p < 2; p++) {
                int k = bk + p * 16;
                size_t go = (size_t)(k0 + k) * Fq + n0 + bnc*4;
                cpa16(sb + (uint32_t)(B1B + s*BU_SZ + k*BU_STR + bnc*4)*4, B1 + go);
                cpa16(sb + (uint32_t)(B3B + s*BU_SZ + k*BU_STR + bnc*4)*4, B3 + go);
            }
            cpa_commit();
        }
        if (kt == 0) continue;
        if (kt < KT) cpa_wait1(); else cpa_wait0();
        __syncthreads();
        int s = (kt - 1) & 1;
        const uint32_t* Asm  = sm + s*A_SZ;
        const uint32_t* B1sm = sm + B1B + s*BU_SZ;
        const uint32_t* B3sm = sm + B3B + s*BU_SZ;
        #pragma unroll
        for (int kk = 0; kk < 4; kk++) {
            int kb = kk * 8;
            uint32_t a[2][4];
            #pragma unroll
            for (int mi = 0; mi < 2; mi++) {
                int rb = wm + mi * 16;
                a[mi][0] = Asm[(rb + lr     )*A_STR + kb + lc    ];
                a[mi][1] = Asm[(rb + lr + 8 )*A_STR + kb + lc    ];
                a[mi][2] = Asm[(rb + lr     )*A_STR + kb + lc + 4];
                a[mi][3] = Asm[(rb + lr + 8 )*A_STR + kb + lc + 4];
            }
            #pragma unroll
            for (int ni = 0; ni < 4; ni++) {
                int nb = wn + ni * 8;
                uint32_t b10 = B1sm[(kb + lc    )*BU_STR + nb + lr];
                uint32_t b11 = B1sm[(kb + lc + 4)*BU_STR + nb + lr];
                uint32_t b30 = B3sm[(kb + lc    )*BU_STR + nb + lr];
                uint32_t b31 = B3sm[(kb + lc + 4)*BU_STR + nb + lr];
                mma_tf32(acc1[0][ni], a[0][0], a[0][1], a[0][2], a[0][3], b10, b11);
                mma_tf32(acc1[1][ni], a[1][0], a[1][1], a[1][2], a[1][3], b10, b11);
                mma_tf32(acc3[0][ni], a[0][0], a[0][1], a[0][2], a[0][3], b30, b31);
                mma_tf32(acc3[1][ni], a[1][0], a[1][1], a[1][2], a[1][3], b30, b31);
            }
        }
        __syncthreads();
    }
    #pragma unroll
    for (int mi = 0; mi < 2; mi++) {
        int row = r0 + wm + mi * 16 + lr;
        #pragma unroll
        for (int ni = 0; ni < 4; ni++) {
            int col = n0 + wn + ni * 8 + lc * 2;
            #pragma unroll
            for (int half = 0; half < 2; half++) {
                float u0 = acc1[mi][ni][half*2+0], u1 = acc1[mi][ni][half*2+1];
                float g0 = u0 / (1.f + expf(-u0));
                float g1 = u1 / (1.f + expf(-u1));
                float2 hv = make_float2(g0 * acc3[mi][ni][half*2+0],
                                        g1 * acc3[mi][ni][half*2+1]);
                *(float2*)(hidden + (size_t)(row + half*8) * Fq + col) = hv;
            }
        }
    }
}

// ---------------- MoE down (tf32 mma, cp.async db): y = hidden @ w2[e] --------------
// grid = (Dq/128, RCAP/128), block 256, dyn smem SMEM_GEMM.
__global__ void __launch_bounds__(256) moe_down_tf32(
        const float* __restrict__ hidden, const float* __restrict__ w2,
        const int* __restrict__ off, float* __restrict__ y) {
    extern __shared__ uint32_t sm[];
    uint32_t sb = (uint32_t)__cvta_generic_to_shared(sm);
    __shared__ int soff[Eq+1];
    int tid = threadIdx.x, lane = tid & 31, wid = tid >> 5;
    if (tid <= Eq) soff[tid] = off[tid];
    __syncthreads();
    int r0 = blockIdx.y * 128;
    if (r0 >= soff[Eq]) return;
    int e = 0;
    #pragma unroll
    for (int i = 0; i < Eq; i++) if (r0 >= soff[i+1]) e = i + 1;
    const float* Bm = w2 + (size_t)e * Fq * Dq;
    int n0 = blockIdx.x * 128;
    int wm = (wid & 3) * 32, wn = (wid >> 2) * 64;
    int lr = lane >> 2, lc = lane & 3;
    float acc[2][8][4] = {};

    int am = tid >> 3, akc = tid & 7;
    int bk = tid >> 5, bnc = tid & 31;

    const int KT = Fq >> 5;   // 128
    #pragma unroll 1
    for (int kt = 0; kt < KT + 1; kt++) {
        if (kt < KT) {
            int s = kt & 1, k0 = kt << 5;
            #pragma unroll
            for (int p = 0; p < 4; p++) {
                int m = am + p * 32;
                cpa16(sb + (uint32_t)(s*A_SZ + m*A_STR + akc*4)*4,
                      hidden + (size_t)(r0 + m) * Fq + k0 + akc*4);
            }
            #pragma unroll
            for (int p = 0; p < 4; p++) {
                int k = bk + p * 8;
                cpa16(sb + (uint32_t)(2*A_SZ + s*B_SZ + k*B_STR + bnc*4)*4,
                      Bm + (size_t)(k0 + k) * Dq + n0 + bnc*4);
            }
            cpa_commit();
        }
        if (kt == 0) continue;
        if (kt < KT) cpa_wait1(); else cpa_wait0();
        __syncthreads();
        int s = (kt - 1) & 1;
        const uint32_t* Asm = sm + s*A_SZ;
        const uint32_t* Bsm = sm + 2*A_SZ + s*B_SZ;
        #pragma unroll
        for (int kk = 0; kk < 4; kk++) {
            int kb = kk * 8;
            uint32_t a[2][4];
            #pragma unroll
            for (int mi = 0; mi < 2; mi++) {
                int rb = wm + mi * 16;
                a[mi][0] = Asm[(rb + lr     )*A_STR + kb + lc    ];
                a[mi][1] = Asm[(rb + lr + 8 )*A_STR + kb + lc    ];
                a[mi][2] = Asm[(rb + lr     )*A_STR + kb + lc + 4];
                a[mi][3] = Asm[(rb + lr + 8 )*A_STR + kb + lc + 4];
            }
            #pragma unroll
            for (int ni = 0; ni < 8; ni++) {
                int nb = wn + ni * 8;
                uint32_t b0 = Bsm[(kb + lc    )*B_STR + nb + lr];
                uint32_t b1 = Bsm[(kb + lc + 4)*B_STR + nb + lr];
                mma_tf32(acc[0][ni], a[0][0], a[0][1], a[0][2], a[0][3], b0, b1);
                mma_tf32(acc[1][ni], a[1][0], a[1][1], a[1][2], a[1][3], b0, b1);
            }
        }
        __syncthreads();
    }
    #pragma unroll
    for (int mi = 0; mi < 2; mi++) {
        int row = r0 + wm + mi * 16 + lr;
        #pragma unroll
        for (int ni = 0; ni < 8; ni++) {
            int col = n0 + wn + ni * 8 + lc * 2;
            *(float2*)(y + (size_t)row * Dq + col) =
                make_float2(acc[mi][ni][0], acc[mi][ni][1]);
            *(float2*)(y + (size_t)(row + 8) * Dq + col) =
                make_float2(acc[mi][ni][2], acc[mi][ni][3]);
        }
    }
}

// ---------------- combine: out = h + w0*y[p0] + w1*y[p1] ----------------
__global__ void combine_kernel(const float* __restrict__ h, const float* __restrict__ y,
                               const int* __restrict__ rowpos, const float* __restrict__ topv,
                               float* __restrict__ out) {
    int idx = blockIdx.x * 256 + threadIdx.x;   // over Tq*Dq
    int t = idx >> 10;
    int d = idx & 1023;
    int p0 = rowpos[t*2], p1 = rowpos[t*2+1];
    float w0 = topv[t*2], w1 = topv[t*2+1];
    out[idx] = h[idx] + w0 * y[(size_t)p0 * Dq + d] + w1 * y[(size_t)p1 * Dq + d];
}

// ---------------- launch ----------------
extern "C" void kernel_launch(void* const* d_in, const int* in_sizes, int n_in,
                              void* d_out, int out_size) {
    const float* x    = (const float*)d_in[0];
    const int*   pos  = (const int*)  d_in[1];
    const float* ln1  = (const float*)d_in[2];
    const float* ln2  = (const float*)d_in[3];
    const float* wq   = (const float*)d_in[4];
    const float* wk   = (const float*)d_in[5];
    const float* wv   = (const float*)d_in[6];
    const float* wo   = (const float*)d_in[7];
    const float* gw   = (const float*)d_in[8];
    const float* w1   = (const float*)d_in[9];
    const float* w3   = (const float*)d_in[10];
    const float* w2   = (const float*)d_in[11];
    float* out = (float*)d_out;

    cudaFuncSetAttribute(gemm_tf32,     cudaFuncAttributeMaxDynamicSharedMemorySize, SMEM_GEMM);
    cudaFuncSetAttribute(moe_up_tf32,   cudaFuncAttributeMaxDynamicSharedMemorySize, SMEM_UP);
    cudaFuncSetAttribute(moe_down_tf32, cudaFuncAttributeMaxDynamicSharedMemorySize, SMEM_GEMM);

    float *h1, *qb, *kb, *vb, *attnb, *hb, *h2b, *hid, *yb, *topv;
    int *topi, *cnt, *off, *rowtok, *rowpos;
    cudaGetSymbolAddress((void**)&h1,     g_h1);
    cudaGetSymbolAddress((void**)&qb,     g_qb);
    cudaGetSymbolAddress((void**)&kb,     g_kb);
    cudaGetSymbolAddress((void**)&vb,     g_vb);
    cudaGetSymbolAddress((void**)&attnb,  g_attn);
    cudaGetSymbolAddress((void**)&hb,     g_h);
    cudaGetSymbolAddress((void**)&h2b,    g_h2);
    cudaGetSymbolAddress((void**)&hid,    g_hidden);
    cudaGetSymbolAddress((void**)&yb,     g_y);
    cudaGetSymbolAddress((void**)&topv,   g_topv);
    cudaGetSymbolAddress((void**)&topi,   g_topi);
    cudaGetSymbolAddress((void**)&cnt,    g_cnt);
    cudaGetSymbolAddress((void**)&off,    g_off);
    cudaGetSymbolAddress((void**)&rowtok, g_rowtok);
    cudaGetSymbolAddress((void**)&rowpos, g_rowpos);

    dim3 gproj(Dq/128, Tq/128);   // (8, 32)

    rmsnorm_kernel<<<Tq, 256>>>(x, ln1, h1);
    gemm_tf32<<<gproj, 256, SMEM_GEMM>>>(h1, wq, nullptr, qb, Dq, Dq);
    gemm_tf32<<<gproj, 256, SMEM_GEMM>>>(h1, wk, nullptr, kb, Dq, Dq);
    gemm_tf32<<<gproj, 256, SMEM_GEMM>>>(h1, wv, nullptr, vb, Dq, Dq);
    rope_kernel<<<(Tq*Hq*32)/256, 256>>>(qb, kb, pos);
    attn_kernel<<<dim3(Sq/64, Bq*Hq), 256>>>(qb, kb, vb, attnb);
    gemm_tf32<<<gproj, 256, SMEM_GEMM>>>(attnb, wo, x, hb, Dq, Dq);
    rmsnorm_kernel<<<Tq, 256>>>(hb, ln2, h2b);

    zero_cnt_kernel<<<1, 32>>>(cnt);
    gate_kernel<<<Tq, 128>>>(h2b, gw, topi, topv, cnt);
    offsets_kernel<<<1, 32>>>(cnt, off);
    scatter_kernel<<<Eq, 256>>>(topi, off, rowtok, rowpos);
    moe_up_tf32<<<dim3(Fq/64, RCAP/128), 256, SMEM_UP>>>(h2b, w1, w3, off, rowtok, hid);
    moe_down_tf32<<<dim3(Dq/128, RCAP/128), 256, SMEM_GEMM>>>(hid, w2, off, yb);
    combine_kernel<<<(Tq*Dq)/256, 256>>>(hb, yb, rowpos, topv, out);
}

// round 17
// speedup vs baseline: 2.5666x; 1.0001x over previous
#include <cuda_runtime.h>
#include <math.h>
#include <stdint.h>

// ---------------- problem constants ----------------
#define Bq   2
#define Sq   2048
#define Dq   1024
#define Hq   16
#define HDq  64
#define Fq   4096
#define Eq   8
#define Kq   2
#define Tq   (Bq*Sq)          // 4096 tokens
#define RCAP 9216             // 8192 assignments + 8*128 padding, /128

// smem word geometry (32-bit words)
#define A_STR 36
#define A_SZ  (128*A_STR)     // 4608 words per stage
#define B_STR 264             // 256-wide B tile + 8 pad
#define B_SZ  (32*B_STR)      // 8448 words per stage
#define BU_STR 136            // 128-wide B tile + 8 pad (moe_up)
#define BU_SZ (32*BU_STR)     // 4352 words per stage

#define SMEM_GEMM  ((2*A_SZ + 2*B_SZ)*4)            // 104448 B
#define SMEM_UP    ((2*A_SZ + 4*BU_SZ)*4)           // 106496 B

// ---------------- static device scratch ----------------
__device__ float g_h1[Tq*Dq];
__device__ float g_qb[Tq*Dq];
__device__ float g_kb[Tq*Dq];
__device__ float g_vb[Tq*Dq];
__device__ float g_attn[Tq*Dq];
__device__ float g_h[Tq*Dq];
__device__ float g_h2[Tq*Dq];
__device__ int   g_topi[Tq*Kq];
__device__ float g_topv[Tq*Kq];
__device__ int   g_cnt[Eq];
__device__ int   g_off[Eq+1];
__device__ int   g_rowtok[RCAP];
__device__ int   g_rowpos[Tq*Kq];
__device__ float g_hidden[(size_t)RCAP*Fq];
__device__ float g_y[(size_t)RCAP*Dq];

// ---------------- mma / cp.async / ldmatrix helpers ----------------
__device__ __forceinline__ void mma_tf32(float* c,
        uint32_t a0, uint32_t a1, uint32_t a2, uint32_t a3,
        uint32_t b0, uint32_t b1) {
    asm volatile(
        "mma.sync.aligned.m16n8k8.row.col.f32.tf32.tf32.f32 "
        "{%0,%1,%2,%3}, {%4,%5,%6,%7}, {%8,%9}, {%0,%1,%2,%3};\n"
        : "+f"(c[0]), "+f"(c[1]), "+f"(c[2]), "+f"(c[3])
        : "r"(a0), "r"(a1), "r"(a2), "r"(a3), "r"(b0), "r"(b1));
}
__device__ __forceinline__ void ldsm_x4(uint32_t* r, uint32_t addr) {
    asm volatile("ldmatrix.sync.aligned.m8n8.x4.shared.b16 {%0,%1,%2,%3}, [%4];"
        : "=r"(r[0]), "=r"(r[1]), "=r"(r[2]), "=r"(r[3]) : "r"(addr));
}
__device__ __forceinline__ void cpa16(uint32_t dst, const void* src) {
    asm volatile("cp.async.cg.shared.global [%0], [%1], 16;" :: "r"(dst), "l"(src));
}
__device__ __forceinline__ void cpa16z(uint32_t dst, const void* src, int src_sz) {
    asm volatile("cp.async.cg.shared.global [%0], [%1], 16, %2;"
                 :: "r"(dst), "l"(src), "r"(src_sz));
}
__device__ __forceinline__ void cpa_commit() { asm volatile("cp.async.commit_group;"); }
__device__ __forceinline__ void cpa_wait1()  { asm volatile("cp.async.wait_group 1;"); }
__device__ __forceinline__ void cpa_wait0()  { asm volatile("cp.async.wait_group 0;"); }

// ---------------- rmsnorm ----------------
__global__ void rmsnorm_kernel(const float* __restrict__ x,
                               const float* __restrict__ w,
                               float* __restrict__ out) {
    int t = blockIdx.x;
    const float* xr = x + (size_t)t * Dq;
    __shared__ float red[256];
    float s = 0.f;
    for (int d = threadIdx.x; d < Dq; d += 256) { float v = xr[d]; s += v*v; }
    red[threadIdx.x] = s; __syncthreads();
    for (int ofs = 128; ofs > 0; ofs >>= 1) {
        if (threadIdx.x < ofs) red[threadIdx.x] += red[threadIdx.x + ofs];
        __syncthreads();
    }
    float r = rsqrtf(red[0] / (float)Dq + 1e-5f);
    float* o = out + (size_t)t * Dq;
    for (int d = threadIdx.x; d < Dq; d += 256) o[d] = xr[d] * r * w[d];
}

// ---------------- tf32 GEMM 128x256x32, cp.async db, ldmatrix A ----------------
// C[M x N] = A @ B (+Res). grid (N/256, M/128), block 256 (8 warps: 2m x 4n of 64x64).
__global__ void __launch_bounds__(256) gemm_tf32(
        const float* __restrict__ A, const float* __restrict__ B,
        const float* __restrict__ Res, float* __restrict__ C,
        int N, int Kd) {
    extern __shared__ uint32_t sm[];
    uint32_t sb = (uint32_t)__cvta_generic_to_shared(sm);
    int tid = threadIdx.x, lane = tid & 31, wid = tid >> 5;
    int wm = (wid & 1) * 64, wn = (wid >> 1) * 64;
    int m0 = blockIdx.y * 128, n0 = blockIdx.x * 256;
    int lr = lane >> 2, lc = lane & 3;
    // ldmatrix lane address components
    int a_row = wm + (lane & 15);
    int a_colw = (lane >> 4) << 2;         // word offset 0 or 4
    float acc[4][8][4] = {};

    int am = tid >> 3, akc = tid & 7;      // A: 4 chunks, m += 32
    int bkk = tid >> 6, bnc = tid & 63;    // B: 8 chunks, k += 4

    const int KT = Kd >> 5;
    #pragma unroll 1
    for (int kt = 0; kt < KT + 1; kt++) {
        if (kt < KT) {
            int s = kt & 1, k0 = kt << 5;
            #pragma unroll
            for (int p = 0; p < 4; p++) {
                int m = am + p * 32;
                cpa16(sb + (uint32_t)(s*A_SZ + m*A_STR + akc*4)*4,
                      A + (size_t)(m0 + m) * Kd + k0 + akc*4);
            }
            #pragma unroll
            for (int p = 0; p < 8; p++) {
                int k = bkk + p * 4;
                cpa16(sb + (uint32_t)(2*A_SZ + s*B_SZ + k*B_STR + bnc*4)*4,
                      B + (size_t)(k0 + k) * N + n0 + bnc*4);
            }
            cpa_commit();
        }
        if (kt == 0) continue;
        if (kt < KT) cpa_wait1(); else cpa_wait0();
        __syncthreads();
        int s = (kt - 1) & 1;
        uint32_t aBase = sb + (uint32_t)(s*A_SZ + a_row*A_STR + a_colw)*4;
        const uint32_t* Bsm = sm + 2*A_SZ + s*B_SZ;
        #pragma unroll
        for (int kk = 0; kk < 4; kk++) {
            int kb = kk * 8;
            uint32_t a[4][4];
            #pragma unroll
            for (int mi = 0; mi < 4; mi++)
                ldsm_x4(a[mi], aBase + (uint32_t)(mi*16*A_STR + kb)*4);
            #pragma unroll
            for (int ni = 0; ni < 8; ni++) {
                int nb = wn + ni * 8;
                uint32_t b0 = Bsm[(kb + lc    )*B_STR + nb + lr];
                uint32_t b1 = Bsm[(kb + lc + 4)*B_STR + nb + lr];
                #pragma unroll
                for (int mi = 0; mi < 4; mi++)
                    mma_tf32(acc[mi][ni], a[mi][0], a[mi][1], a[mi][2], a[mi][3], b0, b1);
            }
        }
        __syncthreads();
    }
    #pragma unroll
    for (int mi = 0; mi < 4; mi++) {
        int r0 = m0 + wm + mi * 16 + lr;
        #pragma unroll
        for (int ni = 0; ni < 8; ni++) {
            int c0 = n0 + wn + ni * 8 + lc * 2;
            float2 v0 = make_float2(acc[mi][ni][0], acc[mi][ni][1]);
            float2 v1 = make_float2(acc[mi][ni][2], acc[mi][ni][3]);
            if (Res) {
                const float2 r0v = *(const float2*)(Res + (size_t)r0 * N + c0);
                const float2 r1v = *(const float2*)(Res + (size_t)(r0+8) * N + c0);
                v0.x += r0v.x; v0.y += r0v.y; v1.x += r1v.x; v1.y += r1v.y;
            }
            *(float2*)(C + (size_t)r0 * N + c0) = v0;
            *(float2*)(C + (size_t)(r0 + 8) * N + c0) = v1;
        }
    }
}

// ---------------- RoPE (in place on q,k) ----------------
__global__ void rope_kernel(float* __restrict__ q, float* __restrict__ k,
                            const int* __restrict__ pos) {
    int idx = blockIdx.x * 256 + threadIdx.x;       // over Tq*Hq*32
    if (idx >= Tq*Hq*32) return;
    int i = idx & 31;
    int h = (idx >> 5) & (Hq - 1);
    int t = idx >> 9;
    float inv = expf(-(float)i * (9.2103403719761836f / 32.f));
    float ang = (float)pos[t] * inv;
    float sn, cs; sincosf(ang, &sn, &cs);
    size_t base = (size_t)t * Dq + h * HDq + 2 * i;
    float x1 = q[base], x2 = q[base+1];
    q[base]   = x1*cs - x2*sn;
    q[base+1] = x1*sn + x2*cs;
    x1 = k[base]; x2 = k[base+1];
    k[base]   = x1*cs - x2*sn;
    k[base+1] = x1*sn + x2*cs;
}

// ---------------- causal flash attention (fp32) ----------------
__global__ void attn_kernel(const float* __restrict__ q, const float* __restrict__ k,
                            const float* __restrict__ v, float* __restrict__ o) {
    __shared__ float QsT[64*65];
    __shared__ float KsT[64*33];
    __shared__ float PsT[32*65];
    __shared__ float Vs [32*64];
    int tid = threadIdx.x, tx = tid & 15, ty = tid >> 4;
    int bh = blockIdx.y; int b = bh >> 4, h = bh & 15;
    int qt = blockIdx.x; int q0 = qt * 64;
    size_t tokb = (size_t)b * Sq;

    #pragma unroll
    for (int l = 0; l < 4; l++) {
        int idx = l*256 + tid; int m = idx >> 4, d4 = idx & 15;
        float4 val = *(const float4*)(q + (tokb + q0 + m) * Dq + h*HDq + d4*4);
        QsT[(d4*4+0)*65 + m] = val.x; QsT[(d4*4+1)*65 + m] = val.y;
        QsT[(d4*4+2)*65 + m] = val.z; QsT[(d4*4+3)*65 + m] = val.w;
    }
    float accO[4][4] = {};
    float mrow[4], lrow[4];
    #pragma unroll
    for (int i = 0; i < 4; i++) { mrow[i] = -1e30f; lrow[i] = 0.f; }
    __syncthreads();

    int ktmax = 2*qt + 1;
    for (int kt = 0; kt <= ktmax; kt++) {
        int k0 = kt * 32;
        #pragma unroll
        for (int l = 0; l < 2; l++) {
            int idx = l*256 + tid; int m = idx >> 4, d4 = idx & 15;
            float4 kv = *(const float4*)(k + (tokb + k0 + m) * Dq + h*HDq + d4*4);
            KsT[(d4*4+0)*33 + m] = kv.x; KsT[(d4*4+1)*33 + m] = kv.y;
            KsT[(d4*4+2)*33 + m] = kv.z; KsT[(d4*4+3)*33 + m] = kv.w;
            float4 vv = *(const float4*)(v + (tokb + k0 + m) * Dq + h*HDq + d4*4);
            *(float4*)(&Vs[m*64 + d4*4]) = vv;
        }
        __syncthreads();

        float s[4][2] = {};
        #pragma unroll 16
        for (int d = 0; d < 64; d++) {
            float a0 = QsT[d*65 + ty*4+0], a1 = QsT[d*65 + ty*4+1];
            float a2 = QsT[d*65 + ty*4+2], a3 = QsT[d*65 + ty*4+3];
            float b0 = KsT[d*33 + tx*2+0], b1 = KsT[d*33 + tx*2+1];
            s[0][0] += a0*b0; s[0][1] += a0*b1;
            s[1][0] += a1*b0; s[1][1] += a1*b1;
            s[2][0] += a2*b0; s[2][1] += a2*b1;
            s[3][0] += a3*b0; s[3][1] += a3*b1;
        }
        bool domask = (kt >= 2*qt);
        #pragma unroll
        for (int i = 0; i < 4; i++)
            #pragma unroll
            for (int j = 0; j < 2; j++) {
                float val = s[i][j] * 0.125f;
                if (domask && (k0 + tx*2 + j) > (q0 + ty*4 + i)) val = -1.0e9f;
                s[i][j] = val;
            }
        #pragma unroll
        for (int i = 0; i < 4; i++) {
            float m_ = fmaxf(s[i][0], s[i][1]);
            #pragma unroll
            for (int ofs = 8; ofs; ofs >>= 1)
                m_ = fmaxf(m_, __shfl_xor_sync(0xffffffffu, m_, ofs));
            float newm = fmaxf(mrow[i], m_);
            float sum = 0.f;
            #pragma unroll
            for (int j = 0; j < 2; j++) {
                float p = __expf(s[i][j] - newm); s[i][j] = p; sum += p;
            }
            #pragma unroll
            for (int ofs = 8; ofs; ofs >>= 1)
                sum += __shfl_xor_sync(0xffffffffu, sum, ofs);
            float corr = __expf(mrow[i] - newm);
            lrow[i] = lrow[i] * corr + sum;
            mrow[i] = newm;
            #pragma unroll
            for (int c = 0; c < 4; c++) accO[i][c] *= corr;
        }
        #pragma unroll
        for (int i = 0; i < 4; i++)
            #pragma unroll
            for (int j = 0; j < 2; j++)
                PsT[(tx*2 + j)*65 + ty*4 + i] = s[i][j];
        __syncthreads();
        #pragma unroll
        for (int n = 0; n < 32; n++) {
            float p0 = PsT[n*65 + ty*4+0], p1 = PsT[n*65 + ty*4+1];
            float p2 = PsT[n*65 + ty*4+2], p3 = PsT[n*65 + ty*4+3];
            float4 vv = *(const float4*)(&Vs[n*64 + tx*4]);
            accO[0][0] += p0*vv.x; accO[0][1] += p0*vv.y; accO[0][2] += p0*vv.z; accO[0][3] += p0*vv.w;
            accO[1][0] += p1*vv.x; accO[1][1] += p1*vv.y; accO[1][2] += p1*vv.z; accO[1][3] += p1*vv.w;
            accO[2][0] += p2*vv.x; accO[2][1] += p2*vv.y; accO[2][2] += p2*vv.z; accO[2][3] += p2*vv.w;
            accO[3][0] += p3*vv.x; accO[3][1] += p3*vv.y; accO[3][2] += p3*vv.z; accO[3][3] += p3*vv.w;
        }
        __syncthreads();
    }
    #pragma unroll
    for (int i = 0; i < 4; i++) {
        float invl = 1.f / lrow[i];
        float4 ov = make_float4(accO[i][0]*invl, accO[i][1]*invl,
                                accO[i][2]*invl, accO[i][3]*invl);
        *(float4*)(o + (tokb + q0 + ty*4 + i) * Dq + h*HDq + tx*4) = ov;
    }
}

// ---------------- MoE gate ----------------
__global__ void gate_kernel(const float* __restrict__ h2, const float* __restrict__ gw,
                            int* __restrict__ topi, float* __restrict__ topv,
                            int* __restrict__ cnt) {
    int t = blockIdx.x;
    __shared__ float part[128*Eq];
    __shared__ float logit[Eq];
    float acc[Eq] = {};
    const float* x = h2 + (size_t)t * Dq;
    for (int d = threadIdx.x; d < Dq; d += 128) {
        float xv = x[d];
        #pragma unroll
        for (int e = 0; e < Eq; e++) acc[e] += xv * gw[d*Eq + e];
    }
    #pragma unroll
    for (int e = 0; e < Eq; e++) part[threadIdx.x*Eq + e] = acc[e];
    __syncthreads();
    if (threadIdx.x < Eq) {
        float s = 0.f;
        for (int i = 0; i < 128; i++) s += part[i*Eq + threadIdx.x];
        logit[threadIdx.x] = s;
    }
    __syncthreads();
    if (threadIdx.x == 0) {
        float mx = logit[0];
        #pragma unroll
        for (int e = 1; e < Eq; e++) mx = fmaxf(mx, logit[e]);
        float p[Eq];
        #pragma unroll
        for (int e = 0; e < Eq; e++) p[e] = expf(logit[e] - mx);
        int i0 = 0;
        #pragma unroll
        for (int e = 1; e < Eq; e++) if (p[e] > p[i0]) i0 = e;
        int i1 = (i0 == 0) ? 1 : 0;
        #pragma unroll
        for (int e = 0; e < Eq; e++) if (e != i0 && p[e] > p[i1]) i1 = e;
        float inv = 1.f / (p[i0] + p[i1]);
        topi[t*2]   = i0; topi[t*2+1] = i1;
        topv[t*2]   = p[i0]*inv; topv[t*2+1] = p[i1]*inv;
        atomicAdd(&cnt[i0], 1);
        atomicAdd(&cnt[i1], 1);
    }
}

__global__ void zero_cnt_kernel(int* cnt) {
    if (threadIdx.x < Eq) cnt[threadIdx.x] = 0;
}

__global__ void offsets_kernel(const int* __restrict__ cnt, int* __restrict__ off) {
    if (threadIdx.x == 0) {
        int acc = 0; off[0] = 0;
        for (int e = 0; e < Eq; e++) { acc += (cnt[e] + 127) & ~127; off[e+1] = acc; }
    }
}

// deterministic scatter
__global__ void scatter_kernel(const int* __restrict__ topi, const int* __restrict__ off,
                               int* __restrict__ rowtok, int* __restrict__ rowpos) {
    int e = blockIdx.x;
    __shared__ int sflag[256];
    __shared__ int sbase;
    int base = off[e];
    if (threadIdx.x == 0) sbase = 0;
    __syncthreads();
    for (int c = 0; c < Tq*Kq; c += 256) {
        int a = c + threadIdx.x;
        int f = (topi[a] == e) ? 1 : 0;
        sflag[threadIdx.x] = f;
        __syncthreads();
        for (int ofs = 1; ofs < 256; ofs <<= 1) {
            int v = (threadIdx.x >= ofs) ? sflag[threadIdx.x - ofs] : 0;
            __syncthreads();
            sflag[threadIdx.x] += v;
            __syncthreads();
        }
        if (f) {
            int pos = base + sbase + sflag[threadIdx.x] - 1;
            rowtok[pos] = a >> 1;
            rowpos[a] = pos;
        }
        __syncthreads();
        if (threadIdx.x == 0) sbase += sflag[255];
        __syncthreads();
    }
    for (int p = base + sbase + threadIdx.x; p < off[e+1]; p += 256) rowtok[p] = -1;
}

// ---------------- MoE up: 128x128 tile (dual), warp 64x32 per matrix --------------
// grid = (Fq/128, RCAP/128), block 256, dyn smem SMEM_UP.
__global__ void __launch_bounds__(256) moe_up_tf32(
        const float* __restrict__ h2, const float* __restrict__ w1,
        const float* __restrict__ w3, const int* __restrict__ off,
        const int* __restrict__ rowtok, float* __restrict__ hidden) {
    extern __shared__ uint32_t sm[];
    uint32_t sb = (uint32_t)__cvta_generic_to_shared(sm);
    __shared__ int stok[128];
    __shared__ int soff[Eq+1];
    int tid = threadIdx.x, lane = tid & 31, wid = tid >> 5;
    if (tid <= Eq) soff[tid] = off[tid];
    __syncthreads();
    int r0 = blockIdx.y * 128;
    if (r0 >= soff[Eq]) return;
    int e = 0;
    #pragma unroll
    for (int i = 0; i < Eq; i++) if (r0 >= soff[i+1]) e = i + 1;
    if (tid < 128) stok[tid] = rowtok[r0 + tid];
    __syncthreads();
    const float* B1 = w1 + (size_t)e * Dq * Fq;
    const float* B3 = w3 + (size_t)e * Dq * Fq;
    int n0 = blockIdx.x * 128;
    int wm = (wid & 1) * 64, wn = (wid >> 1) * 32;
    int lr = lane >> 2, lc = lane & 3;
    int a_row = wm + (lane & 15);
    int a_colw = (lane >> 4) << 2;
    float acc1[4][4][4] = {}, acc3[4][4][4] = {};

    int am = tid >> 3, akc = tid & 7;
    int buk = tid >> 5, bunc = tid & 31;
    const int B1B = 2*A_SZ, B3B = 2*A_SZ + 2*BU_SZ;   // word bases

    const int KT = Dq >> 5;   // 32
    #pragma unroll 1
    for (int kt = 0; kt < KT + 1; kt++) {
        if (kt < KT) {
            int s = kt & 1, k0 = kt << 5;
            #pragma unroll
            for (int p = 0; p < 4; p++) {
                int m = am + p * 32;
                int tok = stok[m];
                const float* src = (tok >= 0) ?
                    h2 + (size_t)tok * Dq + k0 + akc*4 : h2;
                cpa16z(sb + (uint32_t)(s*A_SZ + m*A_STR + akc*4)*4, src,
                       (tok >= 0) ? 16 : 0);
            }
            #pragma unroll
            for (int p = 0; p < 4; p++) {
                int k = buk + p * 8;
                size_t go = (size_t)(k0 + k) * Fq + n0 + bunc*4;
                cpa16(sb + (uint32_t)(B1B + s*BU_SZ + k*BU_STR + bunc*4)*4, B1 + go);
                cpa16(sb + (uint32_t)(B3B + s*BU_SZ + k*BU_STR + bunc*4)*4, B3 + go);
            }
            cpa_commit();
        }
        if (kt == 0) continue;
        if (kt < KT) cpa_wait1(); else cpa_wait0();
        __syncthreads();
        int s = (kt - 1) & 1;
        uint32_t aBase = sb + (uint32_t)(s*A_SZ + a_row*A_STR + a_colw)*4;
        const uint32_t* B1sm = sm + B1B + s*BU_SZ;
        const uint32_t* B3sm = sm + B3B + s*BU_SZ;
        #pragma unroll
        for (int kk = 0; kk < 4; kk++) {
            int kb = kk * 8;
            uint32_t a[4][4];
            #pragma unroll
            for (int mi = 0; mi < 4; mi++)
                ldsm_x4(a[mi], aBase + (uint32_t)(mi*16*A_STR + kb)*4);
            #pragma unroll
            for (int ni = 0; ni < 4; ni++) {
                int nb = wn + ni * 8;
                uint32_t b10 = B1sm[(kb + lc    )*BU_STR + nb + lr];
                uint32_t b11 = B1sm[(kb + lc + 4)*BU_STR + nb + lr];
                uint32_t b30 = B3sm[(kb + lc    )*BU_STR + nb + lr];
                uint32_t b31 = B3sm[(kb + lc + 4)*BU_STR + nb + lr];
                #pragma unroll
                for (int mi = 0; mi < 4; mi++) {
                    mma_tf32(acc1[mi][ni], a[mi][0], a[mi][1], a[mi][2], a[mi][3], b10, b11);
                    mma_tf32(acc3[mi][ni], a[mi][0], a[mi][1], a[mi][2], a[mi][3], b30, b31);
                }
            }
        }
        __syncthreads();
    }
    #pragma unroll
    for (int mi = 0; mi < 4; mi++) {
        int row = r0 + wm + mi * 16 + lr;
        #pragma unroll
        for (int ni = 0; ni < 4; ni++) {
            int col = n0 + wn + ni * 8 + lc * 2;
            #pragma unroll
            for (int half = 0; half < 2; half++) {
                float u0 = acc1[mi][ni][half*2+0], u1 = acc1[mi][ni][half*2+1];
                float g0 = u0 / (1.f + expf(-u0));
                float g1 = u1 / (1.f + expf(-u1));
                float2 hv = make_float2(g0 * acc3[mi][ni][half*2+0],
                                        g1 * acc3[mi][ni][half*2+1]);
                *(float2*)(hidden + (size_t)(row + half*8) * Fq + col) = hv;
            }
        }
    }
}

// ---------------- MoE down: 128x256 tile, warp 64x64 ----------------
// grid = (Dq/256, RCAP/128), block 256, dyn smem SMEM_GEMM.
__global__ void __launch_bounds__(256) moe_down_tf32(
        const float* __restrict__ hidden, const float* __restrict__ w2,
        const int* __restrict__ off, float* __restrict__ y) {
    extern __shared__ uint32_t sm[];
    uint32_t sb = (uint32_t)__cvta_generic_to_shared(sm);
    __shared__ int soff[Eq+1];
    int tid = threadIdx.x, lane = tid & 31, wid = tid >> 5;
    if (tid <= Eq) soff[tid] = off[tid];
    __syncthreads();
    int r0 = blockIdx.y * 128;
    if (r0 >= soff[Eq]) return;
    int e = 0;
    #pragma unroll
    for (int i = 0; i < Eq; i++) if (r0 >= soff[i+1]) e = i + 1;
    const float* Bm = w2 + (size_t)e * Fq * Dq;
    int n0 = blockIdx.x * 256;
    int wm = (wid & 1) * 64, wn = (wid >> 1) * 64;
    int lr = lane >> 2, lc = lane & 3;
    int a_row = wm + (lane & 15);
    int a_colw = (lane >> 4) << 2;
    float acc[4][8][4] = {};

    int am = tid >> 3, akc = tid & 7;
    int bkk = tid >> 6, bnc = tid & 63;

    const int KT = Fq >> 5;   // 128
    #pragma unroll 1
    for (int kt = 0; kt < KT + 1; kt++) {
        if (kt < KT) {
            int s = kt & 1, k0 = kt << 5;
            #pragma unroll
            for (int p = 0; p < 4; p++) {
                int m = am + p * 32;
                cpa16(sb + (uint32_t)(s*A_SZ + m*A_STR + akc*4)*4,
                      hidden + (size_t)(r0 + m) * Fq + k0 + akc*4);
            }
            #pragma unroll
            for (int p = 0; p < 8; p++) {
                int k = bkk + p * 4;
                cpa16(sb + (uint32_t)(2*A_SZ + s*B_SZ + k*B_STR + bnc*4)*4,
                      Bm + (size_t)(k0 + k) * Dq + n0 + bnc*4);
            }
            cpa_commit();
        }
        if (kt == 0) continue;
        if (kt < KT) cpa_wait1(); else cpa_wait0();
        __syncthreads();
        int s = (kt - 1) & 1;
        uint32_t aBase = sb + (uint32_t)(s*A_SZ + a_row*A_STR + a_colw)*4;
        const uint32_t* Bsm = sm + 2*A_SZ + s*B_SZ;
        #pragma unroll
        for (int kk = 0; kk < 4; kk++) {
            int kb = kk * 8;
            uint32_t a[4][4];
            #pragma unroll
            for (int mi = 0; mi < 4; mi++)
                ldsm_x4(a[mi], aBase + (uint32_t)(mi*16*A_STR + kb)*4);
            #pragma unroll
            for (int ni = 0; ni < 8; ni++) {
                int nb = wn + ni * 8;
                uint32_t b0 = Bsm[(kb + lc    )*B_STR + nb + lr];
                uint32_t b1 = Bsm[(kb + lc + 4)*B_STR + nb + lr];
                #pragma unroll
                for (int mi = 0; mi < 4; mi++)
                    mma_tf32(acc[mi][ni], a[mi][0], a[mi][1], a[mi][2], a[mi][3], b0, b1);
            }
        }
        __syncthreads();
    }
    #pragma unroll
    for (int mi = 0; mi < 4; mi++) {
        int row = r0 + wm + mi * 16 + lr;
        #pragma unroll
        for (int ni = 0; ni < 8; ni++) {
            int col = n0 + wn + ni * 8 + lc * 2;
            *(float2*)(y + (size_t)row * Dq + col) =
                make_float2(acc[mi][ni][0], acc[mi][ni][1]);
            *(float2*)(y + (size_t)(row + 8) * Dq + col) =
                make_float2(acc[mi][ni][2], acc[mi][ni][3]);
        }
    }
}

// ---------------- combine: out = h + w0*y[p0] + w1*y[p1] ----------------
__global__ void combine_kernel(const float* __restrict__ h, const float* __restrict__ y,
                               const int* __restrict__ rowpos, const float* __restrict__ topv,
                               float* __restrict__ out) {
    int idx = blockIdx.x * 256 + threadIdx.x;   // over Tq*Dq
    int t = idx >> 10;
    int d = idx & 1023;
    int p0 = rowpos[t*2], p1 = rowpos[t*2+1];
    float w0 = topv[t*2], w1 = topv[t*2+1];
    out[idx] = h[idx] + w0 * y[(size_t)p0 * Dq + d] + w1 * y[(size_t)p1 * Dq + d];
}

// ---------------- launch ----------------
extern "C" void kernel_launch(void* const* d_in, const int* in_sizes, int n_in,
                              void* d_out, int out_size) {
    const float* x    = (const float*)d_in[0];
    const int*   pos  = (const int*)  d_in[1];
    const float* ln1  = (const float*)d_in[2];
    const float* ln2  = (const float*)d_in[3];
    const float* wq   = (const float*)d_in[4];
    const float* wk   = (const float*)d_in[5];
    const float* wv   = (const float*)d_in[6];
    const float* wo   = (const float*)d_in[7];
    const float* gw   = (const float*)d_in[8];
    const float* w1   = (const float*)d_in[9];
    const float* w3   = (const float*)d_in[10];
    const float* w2   = (const float*)d_in[11];
    float* out = (float*)d_out;

    cudaFuncSetAttribute(gemm_tf32,     cudaFuncAttributeMaxDynamicSharedMemorySize, SMEM_GEMM);
    cudaFuncSetAttribute(moe_up_tf32,   cudaFuncAttributeMaxDynamicSharedMemorySize, SMEM_UP);
    cudaFuncSetAttribute(moe_down_tf32, cudaFuncAttributeMaxDynamicSharedMemorySize, SMEM_GEMM);

    float *h1, *qb, *kb, *vb, *attnb, *hb, *h2b, *hid, *yb, *topv;
    int *topi, *cnt, *off, *rowtok, *rowpos;
    cudaGetSymbolAddress((void**)&h1,     g_h1);
    cudaGetSymbolAddress((void**)&qb,     g_qb);
    cudaGetSymbolAddress((void**)&kb,     g_kb);
    cudaGetSymbolAddress((void**)&vb,     g_vb);
    cudaGetSymbolAddress((void**)&attnb,  g_attn);
    cudaGetSymbolAddress((void**)&hb,     g_h);
    cudaGetSymbolAddress((void**)&h2b,    g_h2);
    cudaGetSymbolAddress((void**)&hid,    g_hidden);
    cudaGetSymbolAddress((void**)&yb,     g_y);
    cudaGetSymbolAddress((void**)&topv,   g_topv);
    cudaGetSymbolAddress((void**)&topi,   g_topi);
    cudaGetSymbolAddress((void**)&cnt,    g_cnt);
    cudaGetSymbolAddress((void**)&off,    g_off);
    cudaGetSymbolAddress((void**)&rowtok, g_rowtok);
    cudaGetSymbolAddress((void**)&rowpos, g_rowpos);

    dim3 gproj(Dq/256, Tq/128);   // (4, 32)

    rmsnorm_kernel<<<Tq, 256>>>(x, ln1, h1);
    gemm_tf32<<<gproj, 256, SMEM_GEMM>>>(h1, wq, nullptr, qb, Dq, Dq);
    gemm_tf32<<<gproj, 256, SMEM_GEMM>>>(h1, wk, nullptr, kb, Dq, Dq);
    gemm_tf32<<<gproj, 256, SMEM_GEMM>>>(h1, wv, nullptr, vb, Dq, Dq);
    rope_kernel<<<(Tq*Hq*32)/256, 256>>>(qb, kb, pos);
    attn_kernel<<<dim3(Sq/64, Bq*Hq), 256>>>(qb, kb, vb, attnb);
    gemm_tf32<<<gproj, 256, SMEM_GEMM>>>(attnb, wo, x, hb, Dq, Dq);
    rmsnorm_kernel<<<Tq, 256>>>(hb, ln2, h2b);

    zero_cnt_kernel<<<1, 32>>>(cnt);
    gate_kernel<<<Tq, 128>>>(h2b, gw, topi, topv, cnt);
    offsets_kernel<<<1, 32>>>(cnt, off);
    scatter_kernel<<<Eq, 256>>>(topi, off, rowtok, rowpos);
    moe_up_tf32<<<dim3(Fq/128, RCAP/128), 256, SMEM_UP>>>(h2b, w1, w3, off, rowtok, hid);
    moe_down_tf32<<<dim3(Dq/256, RCAP/128), 256, SMEM_GEMM>>>(hid, w2, off, yb);
    combine_kernel<<<(Tq*Dq)/256, 256>>>(hb, yb, rowpos, topv, out);
}